// round 1
// baseline (speedup 1.0000x reference)
#include <cuda_runtime.h>
#include <cuda_bf16.h>
#include <math.h>

// Problem constants
#define BB   4
#define TT   2048
#define EMB  1024
#define NH   16
#define HD   64
#define MM   (BB * TT)          // 8192 rows

// Scratch in device globals (no allocation allowed)
__device__ float g_q[BB * NH * TT * HD];   // [b,h,t,d]
__device__ float g_k[BB * NH * TT * HD];
__device__ float g_v[BB * NH * TT * HD];
__device__ float g_o[MM * EMB];            // [b*t, e]

// ---------------------------------------------------------------------------
// GEMM: C[M=8192, N=1024] = A[8192,1024] @ W[1024,1024] + bias
// 64x64 tile, BK=16, 256 threads, 4x4 micro-tile per thread.
// permute=1: write out as [b, h, t, d] (n = h*64+d) for attention consumption.
// ---------------------------------------------------------------------------
__global__ __launch_bounds__(256, 2)
void gemm64(const float* __restrict__ A, const float* __restrict__ W,
            const float* __restrict__ bias, float* __restrict__ C, int permute)
{
    __shared__ float As[16 * 68];   // [k][m], padded stride 68
    __shared__ float Bs[16 * 64];   // [k][n]

    const int tid = threadIdx.x;
    const int tx = tid & 15;
    const int ty = tid >> 4;
    const int n0 = blockIdx.x * 64;
    const int m0 = blockIdx.y * 64;

    // load indices
    const int arow = tid >> 2;            // 0..63
    const int acol = (tid & 3) * 4;       // 0,4,8,12
    const int brow = tid >> 4;            // 0..15
    const int bcol = (tid & 15) * 4;      // 0..60

    const float* Aptr = A + (size_t)(m0 + arow) * EMB + acol;
    const float* Wptr = W + (size_t)brow * EMB + n0 + bcol;

    float acc[4][4] = {};

    for (int k0 = 0; k0 < EMB; k0 += 16) {
        float4 av = *(const float4*)(Aptr + k0);
        float4 wv = *(const float4*)(Wptr + (size_t)k0 * EMB);
        As[(acol + 0) * 68 + arow] = av.x;
        As[(acol + 1) * 68 + arow] = av.y;
        As[(acol + 2) * 68 + arow] = av.z;
        As[(acol + 3) * 68 + arow] = av.w;
        *(float4*)&Bs[brow * 64 + bcol] = wv;
        __syncthreads();

#pragma unroll
        for (int k = 0; k < 16; k++) {
            float4 a = *(const float4*)&As[k * 68 + 4 * ty];
            float4 b = *(const float4*)&Bs[k * 64 + 4 * tx];
            float ar[4] = {a.x, a.y, a.z, a.w};
            float br[4] = {b.x, b.y, b.z, b.w};
#pragma unroll
            for (int i = 0; i < 4; i++)
#pragma unroll
                for (int j = 0; j < 4; j++)
                    acc[i][j] = fmaf(ar[i], br[j], acc[i][j]);
        }
        __syncthreads();
    }

    float4 bi = *(const float4*)&bias[n0 + 4 * tx];
    float bv[4] = {bi.x, bi.y, bi.z, bi.w};

#pragma unroll
    for (int i = 0; i < 4; i++) {
        int m = m0 + 4 * ty + i;
        float4 res;
        res.x = acc[i][0] + bv[0];
        res.y = acc[i][1] + bv[1];
        res.z = acc[i][2] + bv[2];
        res.w = acc[i][3] + bv[3];
        if (permute) {
            int b = m >> 11;            // m / TT
            int t = m & (TT - 1);
            int h = n0 >> 6;            // head index (n tile aligned with head)
            float* dst = C + (((size_t)(b * NH + h) * TT + t) * HD) + 4 * tx;
            *(float4*)dst = res;
        } else {
            float* dst = C + (size_t)m * EMB + n0 + 4 * tx;
            *(float4*)dst = res;
        }
    }
}

// ---------------------------------------------------------------------------
// Causal flash attention, fp32. One CTA per (b, h, 64-query tile).
// Q,K stored d-major (transposed) in SMEM -> conflict-free float4 LDS in QK.
// ---------------------------------------------------------------------------
#define SROW 68   // padded row stride (272B: 16B aligned, bank offset 4)

__global__ __launch_bounds__(256, 2)
void flashattn(const float* __restrict__ Q, const float* __restrict__ K,
               const float* __restrict__ V, float* __restrict__ O)
{
    extern __shared__ float sm[];
    float* Qt   = sm;                 // [d][r]  d*SROW + r
    float* Kt   = sm + 64 * SROW;     // [d][c]
    float* Vs   = sm + 2 * 64 * SROW; // [k][c]
    float* Ss   = sm + 3 * 64 * SROW; // [r][c]
    float* mrow = sm + 4 * 64 * SROW; // 64
    float* lrow = mrow + 64;          // 64
    float* arow = lrow + 64;          // 64

    const int tid = threadIdx.x;
    const int tx = tid & 15;
    const int ty = tid >> 4;
    const int qt = gridDim.x - 1 - blockIdx.x;  // big tiles scheduled first
    const int h  = blockIdx.y;
    const int b  = blockIdx.z;
    const float scale = 0.125f;       // 1/sqrt(64)

    const size_t base_bh = ((size_t)(b * NH + h)) * TT * HD;
    const float* Qg = Q + base_bh + (size_t)qt * 64 * HD;

    const int lr = tid >> 4;          // 0..15
    const int lc = (tid & 15) * 4;    // 0..60

    // Load Q tile transposed, pre-scaled
#pragma unroll
    for (int rr = 0; rr < 4; rr++) {
        int row = lr + rr * 16;
        float4 v = *(const float4*)(Qg + row * HD + lc);
        Qt[(lc + 0) * SROW + row] = v.x * scale;
        Qt[(lc + 1) * SROW + row] = v.y * scale;
        Qt[(lc + 2) * SROW + row] = v.z * scale;
        Qt[(lc + 3) * SROW + row] = v.w * scale;
    }
    if (tid < 64) { mrow[tid] = -3.0e38f; lrow[tid] = 0.0f; }

    float o[4][4] = {};

    for (int j = 0; j <= qt; j++) {
        const float* Kg = K + base_bh + (size_t)j * 64 * HD;
        const float* Vg = V + base_bh + (size_t)j * 64 * HD;
#pragma unroll
        for (int rr = 0; rr < 4; rr++) {
            int row = lr + rr * 16;
            float4 kv = *(const float4*)(Kg + row * HD + lc);
            Kt[(lc + 0) * SROW + row] = kv.x;
            Kt[(lc + 1) * SROW + row] = kv.y;
            Kt[(lc + 2) * SROW + row] = kv.z;
            Kt[(lc + 3) * SROW + row] = kv.w;
            float4 vv = *(const float4*)(Vg + row * HD + lc);
            *(float4*)&Vs[row * SROW + lc] = vv;
        }
        __syncthreads();

        // S = Q K^T  (4x4 per thread)
        float s[4][4] = {};
#pragma unroll 16
        for (int d = 0; d < 64; d++) {
            float4 qv = *(const float4*)&Qt[d * SROW + 4 * ty];
            float4 kv = *(const float4*)&Kt[d * SROW + 4 * tx];
            float qr[4] = {qv.x, qv.y, qv.z, qv.w};
            float kr[4] = {kv.x, kv.y, kv.z, kv.w};
#pragma unroll
            for (int i = 0; i < 4; i++)
#pragma unroll
                for (int jj = 0; jj < 4; jj++)
                    s[i][jj] = fmaf(qr[i], kr[jj], s[i][jj]);
        }

        if (j == qt) {  // diagonal tile: causal mask (strictly-upper masked)
#pragma unroll
            for (int i = 0; i < 4; i++)
#pragma unroll
                for (int jj = 0; jj < 4; jj++)
                    if (4 * tx + jj > 4 * ty + i) s[i][jj] = -3.0e38f;
        }

#pragma unroll
        for (int i = 0; i < 4; i++) {
            float4 sv = make_float4(s[i][0], s[i][1], s[i][2], s[i][3]);
            *(float4*)&Ss[(4 * ty + i) * SROW + 4 * tx] = sv;
        }
        __syncthreads();

        // Online softmax: 4 threads per row (consecutive lanes)
        {
            int row = tid >> 2, sub = tid & 3;
            float* srow = Ss + row * SROW + sub * 16;
            float mx = srow[0];
#pragma unroll
            for (int c = 1; c < 16; c++) mx = fmaxf(mx, srow[c]);
            mx = fmaxf(mx, __shfl_xor_sync(0xffffffffu, mx, 1));
            mx = fmaxf(mx, __shfl_xor_sync(0xffffffffu, mx, 2));
            float mold = mrow[row];
            float mnew = fmaxf(mold, mx);
            float sum = 0.0f;
#pragma unroll
            for (int c = 0; c < 16; c++) {
                float p = __expf(srow[c] - mnew);
                srow[c] = p;
                sum += p;
            }
            sum += __shfl_xor_sync(0xffffffffu, sum, 1);
            sum += __shfl_xor_sync(0xffffffffu, sum, 2);
            if (sub == 0) {
                float al = __expf(mold - mnew);
                arow[row] = al;
                mrow[row] = mnew;
                lrow[row] = lrow[row] * al + sum;
            }
        }
        __syncthreads();

        // O = O*alpha + P V
        float al[4];
#pragma unroll
        for (int i = 0; i < 4; i++) al[i] = arow[4 * ty + i];
#pragma unroll
        for (int i = 0; i < 4; i++)
#pragma unroll
            for (int jj = 0; jj < 4; jj++) o[i][jj] *= al[i];

#pragma unroll 16
        for (int kk = 0; kk < 64; kk++) {
            float4 vv = *(const float4*)&Vs[kk * SROW + 4 * tx];
            float vr[4] = {vv.x, vv.y, vv.z, vv.w};
            float p0 = Ss[(4 * ty + 0) * SROW + kk];
            float p1 = Ss[(4 * ty + 1) * SROW + kk];
            float p2 = Ss[(4 * ty + 2) * SROW + kk];
            float p3 = Ss[(4 * ty + 3) * SROW + kk];
#pragma unroll
            for (int jj = 0; jj < 4; jj++) {
                o[0][jj] = fmaf(p0, vr[jj], o[0][jj]);
                o[1][jj] = fmaf(p1, vr[jj], o[1][jj]);
                o[2][jj] = fmaf(p2, vr[jj], o[2][jj]);
                o[3][jj] = fmaf(p3, vr[jj], o[3][jj]);
            }
        }
        __syncthreads();
    }

    // Normalize and write to [b*t, e] layout
#pragma unroll
    for (int i = 0; i < 4; i++) {
        float inv = 1.0f / lrow[4 * ty + i];
        int t = qt * 64 + 4 * ty + i;
        float* dst = O + ((size_t)(b * TT + t)) * EMB + h * HD + 4 * tx;
        float4 res;
        res.x = o[i][0] * inv;
        res.y = o[i][1] * inv;
        res.z = o[i][2] * inv;
        res.w = o[i][3] * inv;
        *(float4*)dst = res;
    }
}

// ---------------------------------------------------------------------------
// Launch
// ---------------------------------------------------------------------------
extern "C" void kernel_launch(void* const* d_in, const int* in_sizes, int n_in,
                              void* d_out, int out_size)
{
    const float* x  = (const float*)d_in[0];
    const float* Wq = (const float*)d_in[1];
    const float* bq = (const float*)d_in[2];
    const float* Wk = (const float*)d_in[3];
    const float* bk = (const float*)d_in[4];
    const float* Wv = (const float*)d_in[5];
    const float* bv = (const float*)d_in[6];
    const float* Wo = (const float*)d_in[7];
    const float* bo = (const float*)d_in[8];
    float* out = (float*)d_out;

    float *q, *k, *v, *o;
    cudaGetSymbolAddress((void**)&q, g_q);
    cudaGetSymbolAddress((void**)&k, g_k);
    cudaGetSymbolAddress((void**)&v, g_v);
    cudaGetSymbolAddress((void**)&o, g_o);

    const int smem_attn = (4 * 64 * SROW + 3 * 64) * (int)sizeof(float); // 70400 B
    cudaFuncSetAttribute(flashattn, cudaFuncAttributeMaxDynamicSharedMemorySize,
                         smem_attn);

    dim3 gemm_grid(EMB / 64, MM / 64);   // (16, 128)
    gemm64<<<gemm_grid, 256>>>(x, Wq, bq, q, 1);
    gemm64<<<gemm_grid, 256>>>(x, Wk, bk, k, 1);
    gemm64<<<gemm_grid, 256>>>(x, Wv, bv, v, 1);

    dim3 attn_grid(TT / 64, NH, BB);     // (32, 16, 4)
    flashattn<<<attn_grid, 256, smem_attn>>>(q, k, v, o);

    gemm64<<<gemm_grid, 256>>>(o, Wo, bo, out, 0);
}

// round 3
// speedup vs baseline: 1.6391x; 1.6391x over previous
#include <cuda_runtime.h>
#include <cuda_bf16.h>
#include <math.h>
#include <stdint.h>

// Problem constants
#define BB   4
#define TT   2048
#define EMB  1024
#define NH   16
#define HD   64
#define MM   (BB * TT)          // 8192 rows

// ---------------------------------------------------------------------------
// Scratch (device globals; no allocation allowed)
// ---------------------------------------------------------------------------
__device__ float g_q[BB * NH * TT * HD];   // [b,h,t,d]
__device__ float g_k[BB * NH * TT * HD];
__device__ float g_v[BB * NH * TT * HD];
__device__ float g_o[MM * EMB];            // [b*t, e]

// bf16 hi/lo operands, plain row-major
__device__ __nv_bfloat16 g_ahi[MM * EMB];          // A [8192][1024]
__device__ __nv_bfloat16 g_alo[MM * EMB];
__device__ __nv_bfloat16 g_whi[4 * EMB * EMB];     // W^T [N][K] per weight
__device__ __nv_bfloat16 g_wlo[4 * EMB * EMB];

// ---------------------------------------------------------------------------
// Helpers (all plain-sm_103-safe PTX: ldmatrix / mma.sync / cp.async)
// ---------------------------------------------------------------------------
__device__ __forceinline__ uint32_t smem_u32(const void* p) {
    uint32_t a;
    asm("{ .reg .u64 t; cvta.to.shared.u64 t, %1; cvt.u32.u64 %0, t; }"
        : "=r"(a) : "l"(p));
    return a;
}

#define LDSM_X4(R, addr) \
    asm volatile("ldmatrix.sync.aligned.m8n8.x4.shared.b16 {%0,%1,%2,%3}, [%4];" \
        : "=r"((R)[0]), "=r"((R)[1]), "=r"((R)[2]), "=r"((R)[3]) : "r"(addr))

#define MMA16816(C, A, B) \
    asm volatile("mma.sync.aligned.m16n8k16.row.col.f32.bf16.bf16.f32 " \
        "{%0,%1,%2,%3}, {%4,%5,%6,%7}, {%8,%9}, {%0,%1,%2,%3};" \
        : "+f"((C)[0]), "+f"((C)[1]), "+f"((C)[2]), "+f"((C)[3]) \
        : "r"((A)[0]), "r"((A)[1]), "r"((A)[2]), "r"((A)[3]), \
          "r"((B)[0]), "r"((B)[1]))

#define CP_ASYNC16(dst, src) \
    asm volatile("cp.async.cg.shared.global [%0], [%1], 16;" :: "r"(dst), "l"(src))
#define CP_COMMIT() asm volatile("cp.async.commit_group;")
#define CP_WAIT1()  asm volatile("cp.async.wait_group 1;")
#define CP_WAIT0()  asm volatile("cp.async.wait_group 0;")

// ---------------------------------------------------------------------------
// split_x: fp32 [8192,1024] row-major -> hi/lo bf16 row-major
// ---------------------------------------------------------------------------
__global__ __launch_bounds__(256)
void split_x(const float* __restrict__ X, __nv_bfloat16* __restrict__ hi,
             __nv_bfloat16* __restrict__ lo)
{
    int idx = blockIdx.x * 256 + threadIdx.x;    // 2M threads, 4 elems each
    size_t e = (size_t)idx * 4;
    float4 v = *(const float4*)(X + e);

    __nv_bfloat16 h0 = __float2bfloat16(v.x);
    __nv_bfloat16 h1 = __float2bfloat16(v.y);
    __nv_bfloat16 h2 = __float2bfloat16(v.z);
    __nv_bfloat16 h3 = __float2bfloat16(v.w);
    __nv_bfloat16 l0 = __float2bfloat16(v.x - __bfloat162float(h0));
    __nv_bfloat16 l1 = __float2bfloat16(v.y - __bfloat162float(h1));
    __nv_bfloat16 l2 = __float2bfloat16(v.z - __bfloat162float(h2));
    __nv_bfloat16 l3 = __float2bfloat16(v.w - __bfloat162float(h3));

    __nv_bfloat162 hp0 = __halves2bfloat162(h0, h1);
    __nv_bfloat162 hp1 = __halves2bfloat162(h2, h3);
    __nv_bfloat162 lp0 = __halves2bfloat162(l0, l1);
    __nv_bfloat162 lp1 = __halves2bfloat162(l2, l3);
    uint2 hw, lw;
    hw.x = *(uint32_t*)&hp0; hw.y = *(uint32_t*)&hp1;
    lw.x = *(uint32_t*)&lp0; lw.y = *(uint32_t*)&lp1;
    *(uint2*)(hi + e) = hw;
    *(uint2*)(lo + e) = lw;
}

// ---------------------------------------------------------------------------
// split_wt: W [K,N] fp32 -> W^T [N,K] hi/lo bf16 (32x32 smem transpose)
// grid (32, 32), block (32, 8)
// ---------------------------------------------------------------------------
__global__ __launch_bounds__(256)
void split_wt(const float* __restrict__ W, __nv_bfloat16* __restrict__ hi,
              __nv_bfloat16* __restrict__ lo)
{
    __shared__ float ts[32][33];
    const int n0 = blockIdx.x * 32, k0 = blockIdx.y * 32;
    const int tx = threadIdx.x, ty = threadIdx.y;

#pragma unroll
    for (int p = 0; p < 4; p++) {
        int ky = ty + p * 8;
        ts[ky][tx] = W[(size_t)(k0 + ky) * EMB + n0 + tx];
    }
    __syncthreads();
#pragma unroll
    for (int p = 0; p < 4; p++) {
        int ny = ty + p * 8;
        float v = ts[tx][ny];
        __nv_bfloat16 h = __float2bfloat16(v);
        __nv_bfloat16 l = __float2bfloat16(v - __bfloat162float(h));
        size_t off = (size_t)(n0 + ny) * EMB + k0 + tx;
        hi[off] = h;
        lo[off] = l;
    }
}

// ---------------------------------------------------------------------------
// Tensor-core GEMM via mma.sync (bf16 split, 3 terms):
// C[8192,1024] = A@W + bias.  A as hi/lo [M][K] bf16, W^T as hi/lo [N][K] bf16.
// CTA 128x128, BK=32, cp.async double buffer, 8 warps (2x4), warp tile 64x32.
// ---------------------------------------------------------------------------
#define TPAD  40                // smem row stride in bf16 (80B, conflict-free)
#define TSZ   (128 * TPAD)      // elems per tile (128 rows)
#define GSMEM (2 * 4 * TSZ * 2) // bytes: 2 stages x 4 tiles  = 81920

__global__ __launch_bounds__(256)
void gemm_ts(const __nv_bfloat16* __restrict__ Ahi, const __nv_bfloat16* __restrict__ Alo,
             const __nv_bfloat16* __restrict__ Whi, const __nv_bfloat16* __restrict__ Wlo,
             const float* __restrict__ bias, float* __restrict__ C, int permute)
{
    extern __shared__ __align__(128) __nv_bfloat16 sm[];
    const uint32_t sbase = smem_u32(sm);
    const int tid  = threadIdx.x;
    const int lane = tid & 31;
    const int warp = tid >> 5;
    const int wm = warp >> 2;          // 0..1
    const int wn = warp & 3;           // 0..3
    const int n0 = blockIdx.x * 128;
    const int m0 = blockIdx.y * 128;

    const __nv_bfloat16* srcs[4] = {
        Ahi + (size_t)m0 * EMB, Alo + (size_t)m0 * EMB,
        Whi + (size_t)n0 * EMB, Wlo + (size_t)n0 * EMB
    };

    float acc[4][4][4] = {};   // [m-tile][n-tile][reg]

    // ---- stage loader: 4 tiles x 512 chunks of 16B ----
    // chunk c: tile=c/512, row=(c/4)%128, col16=c%4
#define LOAD_STAGE(s, k0)                                                     \
    do {                                                                      \
        _Pragma("unroll")                                                     \
        for (int p = 0; p < 8; p++) {                                         \
            int c = tid + p * 256;                                            \
            int t = c >> 9;                                                   \
            int r = (c >> 2) & 127;                                           \
            int c16 = c & 3;                                                  \
            uint32_t dst = sbase + (((s) * 4 + t) * TSZ + r * TPAD + c16 * 8) * 2; \
            const void* src = srcs[t] + (size_t)r * EMB + (k0) + c16 * 8;     \
            CP_ASYNC16(dst, src);                                             \
        }                                                                     \
        CP_COMMIT();                                                          \
    } while (0)

    LOAD_STAGE(0, 0);

    // fragment addressing (constant per thread)
    const int arow_in = (lane & 7) + ((lane >> 3) & 1) * 8;  // row within m16
    const int ak_half = (lane >> 4) * 8;                     // k offset 0/8
    const int bg      = lane >> 3;                           // B group 0..3
    const int brow_in = (lane & 7) + ((bg >> 1) & 1) * 8;    // row within n16 pair
    const int bk_half = (bg & 1) * 8;

    for (int kt = 0; kt < 32; kt++) {
        const int s = kt & 1;
        if (kt < 31) {
            LOAD_STAGE(s ^ 1, (kt + 1) * 32);
            CP_WAIT1();
        } else {
            CP_WAIT0();
        }
        __syncthreads();

        const uint32_t st = sbase + s * 4 * TSZ * 2;
#pragma unroll
        for (int kc = 0; kc < 32; kc += 16) {
            uint32_t ah[4][4], al[4][4], bh[4][2], bl[4][2];
#pragma unroll
            for (int i = 0; i < 4; i++) {
                int row = wm * 64 + i * 16 + arow_in;
                uint32_t addr = st + (row * TPAD + kc + ak_half) * 2;
                LDSM_X4(ah[i], addr);
                LDSM_X4(al[i], addr + TSZ * 2);
            }
#pragma unroll
            for (int j = 0; j < 2; j++) {
                int nrow = wn * 32 + j * 16 + brow_in;
                uint32_t addr = st + (2 * TSZ + nrow * TPAD + kc + bk_half) * 2;
                uint32_t r4[4];
                LDSM_X4(r4, addr);
                bh[2 * j][0] = r4[0]; bh[2 * j][1] = r4[1];
                bh[2 * j + 1][0] = r4[2]; bh[2 * j + 1][1] = r4[3];
                LDSM_X4(r4, addr + TSZ * 2);
                bl[2 * j][0] = r4[0]; bl[2 * j][1] = r4[1];
                bl[2 * j + 1][0] = r4[2]; bl[2 * j + 1][1] = r4[3];
            }
#pragma unroll
            for (int i = 0; i < 4; i++)
#pragma unroll
                for (int j = 0; j < 4; j++) {
                    MMA16816(acc[i][j], ah[i], bh[j]);
                    MMA16816(acc[i][j], ah[i], bl[j]);
                    MMA16816(acc[i][j], al[i], bh[j]);
                }
        }
        __syncthreads();
    }

    // ---- epilogue ----
    const int ln4 = lane >> 2;     // 0..7
    const int lm4 = lane & 3;      // 0..3
#pragma unroll
    for (int j = 0; j < 4; j++) {
        int n = n0 + wn * 32 + j * 8 + lm4 * 2;
        float2 bj = *(const float2*)(bias + n);
#pragma unroll
        for (int i = 0; i < 4; i++) {
#pragma unroll
            for (int half = 0; half < 2; half++) {
                int m = m0 + wm * 64 + i * 16 + ln4 + half * 8;
                float2 res;
                res.x = acc[i][j][half * 2 + 0] + bj.x;
                res.y = acc[i][j][half * 2 + 1] + bj.y;
                float* dst;
                if (permute) {
                    int b = m >> 11;
                    int t = m & (TT - 1);
                    int h = n >> 6;
                    int d = n & 63;
                    dst = C + (((size_t)(b * NH + h) * TT + t) * HD) + d;
                } else {
                    dst = C + (size_t)m * EMB + n;
                }
                *(float2*)dst = res;
            }
        }
    }
}

// ---------------------------------------------------------------------------
// Causal flash attention, fp32 (validated in R1)
// ---------------------------------------------------------------------------
#define SROW 68

__global__ __launch_bounds__(256, 2)
void flashattn(const float* __restrict__ Q, const float* __restrict__ K,
               const float* __restrict__ V, float* __restrict__ O)
{
    extern __shared__ float smf[];
    float* Qt   = smf;
    float* Kt   = smf + 64 * SROW;
    float* Vs   = smf + 2 * 64 * SROW;
    float* Ss   = smf + 3 * 64 * SROW;
    float* mrow = smf + 4 * 64 * SROW;
    float* lrow = mrow + 64;
    float* arow = lrow + 64;

    const int tid = threadIdx.x;
    const int tx = tid & 15;
    const int ty = tid >> 4;
    const int qt = gridDim.x - 1 - blockIdx.x;
    const int h  = blockIdx.y;
    const int b  = blockIdx.z;
    const float scale = 0.125f;

    const size_t base_bh = ((size_t)(b * NH + h)) * TT * HD;
    const float* Qg = Q + base_bh + (size_t)qt * 64 * HD;

    const int lr = tid >> 4;
    const int lc = (tid & 15) * 4;

#pragma unroll
    for (int rr = 0; rr < 4; rr++) {
        int row = lr + rr * 16;
        float4 v = *(const float4*)(Qg + row * HD + lc);
        Qt[(lc + 0) * SROW + row] = v.x * scale;
        Qt[(lc + 1) * SROW + row] = v.y * scale;
        Qt[(lc + 2) * SROW + row] = v.z * scale;
        Qt[(lc + 3) * SROW + row] = v.w * scale;
    }
    if (tid < 64) { mrow[tid] = -3.0e38f; lrow[tid] = 0.0f; }

    float o[4][4] = {};

    for (int j = 0; j <= qt; j++) {
        const float* Kg = K + base_bh + (size_t)j * 64 * HD;
        const float* Vg = V + base_bh + (size_t)j * 64 * HD;
#pragma unroll
        for (int rr = 0; rr < 4; rr++) {
            int row = lr + rr * 16;
            float4 kv = *(const float4*)(Kg + row * HD + lc);
            Kt[(lc + 0) * SROW + row] = kv.x;
            Kt[(lc + 1) * SROW + row] = kv.y;
            Kt[(lc + 2) * SROW + row] = kv.z;
            Kt[(lc + 3) * SROW + row] = kv.w;
            float4 vv = *(const float4*)(Vg + row * HD + lc);
            *(float4*)&Vs[row * SROW + lc] = vv;
        }
        __syncthreads();

        float s[4][4] = {};
#pragma unroll 16
        for (int d = 0; d < 64; d++) {
            float4 qv = *(const float4*)&Qt[d * SROW + 4 * ty];
            float4 kv = *(const float4*)&Kt[d * SROW + 4 * tx];
            float qr[4] = {qv.x, qv.y, qv.z, qv.w};
            float kr[4] = {kv.x, kv.y, kv.z, kv.w};
#pragma unroll
            for (int i = 0; i < 4; i++)
#pragma unroll
                for (int jj = 0; jj < 4; jj++)
                    s[i][jj] = fmaf(qr[i], kr[jj], s[i][jj]);
        }

        if (j == qt) {
#pragma unroll
            for (int i = 0; i < 4; i++)
#pragma unroll
                for (int jj = 0; jj < 4; jj++)
                    if (4 * tx + jj > 4 * ty + i) s[i][jj] = -3.0e38f;
        }

#pragma unroll
        for (int i = 0; i < 4; i++) {
            float4 sv = make_float4(s[i][0], s[i][1], s[i][2], s[i][3]);
            *(float4*)&Ss[(4 * ty + i) * SROW + 4 * tx] = sv;
        }
        __syncthreads();

        {
            int row = tid >> 2, sub = tid & 3;
            float* srow = Ss + row * SROW + sub * 16;
            float mx = srow[0];
#pragma unroll
            for (int c = 1; c < 16; c++) mx = fmaxf(mx, srow[c]);
            mx = fmaxf(mx, __shfl_xor_sync(0xffffffffu, mx, 1));
            mx = fmaxf(mx, __shfl_xor_sync(0xffffffffu, mx, 2));
            float mold = mrow[row];
            float mnew = fmaxf(mold, mx);
            float sum = 0.0f;
#pragma unroll
            for (int c = 0; c < 16; c++) {
                float p = __expf(srow[c] - mnew);
                srow[c] = p;
                sum += p;
            }
            sum += __shfl_xor_sync(0xffffffffu, sum, 1);
            sum += __shfl_xor_sync(0xffffffffu, sum, 2);
            if (sub == 0) {
                float al = __expf(mold - mnew);
                arow[row] = al;
                mrow[row] = mnew;
                lrow[row] = lrow[row] * al + sum;
            }
        }
        __syncthreads();

        float al[4];
#pragma unroll
        for (int i = 0; i < 4; i++) al[i] = arow[4 * ty + i];
#pragma unroll
        for (int i = 0; i < 4; i++)
#pragma unroll
            for (int jj = 0; jj < 4; jj++) o[i][jj] *= al[i];

#pragma unroll 16
        for (int kk = 0; kk < 64; kk++) {
            float4 vv = *(const float4*)&Vs[kk * SROW + 4 * tx];
            float vr[4] = {vv.x, vv.y, vv.z, vv.w};
            float p0 = Ss[(4 * ty + 0) * SROW + kk];
            float p1 = Ss[(4 * ty + 1) * SROW + kk];
            float p2 = Ss[(4 * ty + 2) * SROW + kk];
            float p3 = Ss[(4 * ty + 3) * SROW + kk];
#pragma unroll
            for (int jj = 0; jj < 4; jj++) {
                o[0][jj] = fmaf(p0, vr[jj], o[0][jj]);
                o[1][jj] = fmaf(p1, vr[jj], o[1][jj]);
                o[2][jj] = fmaf(p2, vr[jj], o[2][jj]);
                o[3][jj] = fmaf(p3, vr[jj], o[3][jj]);
            }
        }
        __syncthreads();
    }

#pragma unroll
    for (int i = 0; i < 4; i++) {
        float inv = 1.0f / lrow[4 * ty + i];
        int t = qt * 64 + 4 * ty + i;
        float* dst = O + ((size_t)(b * TT + t)) * EMB + h * HD + 4 * tx;
        float4 res;
        res.x = o[i][0] * inv;
        res.y = o[i][1] * inv;
        res.z = o[i][2] * inv;
        res.w = o[i][3] * inv;
        *(float4*)dst = res;
    }
}

// ---------------------------------------------------------------------------
// Launch
// ---------------------------------------------------------------------------
extern "C" void kernel_launch(void* const* d_in, const int* in_sizes, int n_in,
                              void* d_out, int out_size)
{
    const float* x  = (const float*)d_in[0];
    const float* Wq = (const float*)d_in[1];
    const float* bq = (const float*)d_in[2];
    const float* Wk = (const float*)d_in[3];
    const float* bk = (const float*)d_in[4];
    const float* Wv = (const float*)d_in[5];
    const float* bv = (const float*)d_in[6];
    const float* Wo = (const float*)d_in[7];
    const float* bo = (const float*)d_in[8];
    float* out = (float*)d_out;

    float *q, *k, *v, *o;
    __nv_bfloat16 *ahi, *alo, *whi, *wlo;
    cudaGetSymbolAddress((void**)&q, g_q);
    cudaGetSymbolAddress((void**)&k, g_k);
    cudaGetSymbolAddress((void**)&v, g_v);
    cudaGetSymbolAddress((void**)&o, g_o);
    cudaGetSymbolAddress((void**)&ahi, g_ahi);
    cudaGetSymbolAddress((void**)&alo, g_alo);
    cudaGetSymbolAddress((void**)&whi, g_whi);
    cudaGetSymbolAddress((void**)&wlo, g_wlo);

    const int smem_attn = (4 * 64 * SROW + 3 * 64) * (int)sizeof(float);
    cudaFuncSetAttribute(flashattn, cudaFuncAttributeMaxDynamicSharedMemorySize,
                         smem_attn);
    cudaFuncSetAttribute(gemm_ts, cudaFuncAttributeMaxDynamicSharedMemorySize,
                         GSMEM);

    const size_t WS = (size_t)EMB * EMB;

    // Split inputs
    split_x<<<(MM * EMB / 4) / 256, 256>>>(x, ahi, alo);
    dim3 wt_grid(EMB / 32, EMB / 32);
    dim3 wt_blk(32, 8);
    split_wt<<<wt_grid, wt_blk>>>(Wq, whi + 0 * WS, wlo + 0 * WS);
    split_wt<<<wt_grid, wt_blk>>>(Wk, whi + 1 * WS, wlo + 1 * WS);
    split_wt<<<wt_grid, wt_blk>>>(Wv, whi + 2 * WS, wlo + 2 * WS);
    split_wt<<<wt_grid, wt_blk>>>(Wo, whi + 3 * WS, wlo + 3 * WS);

    // QKV projections on tensor cores (permuted epilogue)
    dim3 ggrid(EMB / 128, MM / 128);    // (8, 64)
    gemm_ts<<<ggrid, 256, GSMEM>>>(ahi, alo, whi + 0 * WS, wlo + 0 * WS, bq, q, 1);
    gemm_ts<<<ggrid, 256, GSMEM>>>(ahi, alo, whi + 1 * WS, wlo + 1 * WS, bk, k, 1);
    gemm_ts<<<ggrid, 256, GSMEM>>>(ahi, alo, whi + 2 * WS, wlo + 2 * WS, bv, v, 1);

    // Attention (fp32)
    dim3 attn_grid(TT / 64, NH, BB);
    flashattn<<<attn_grid, 256, smem_attn>>>(q, k, v, o);

    // Output projection
    split_x<<<(MM * EMB / 4) / 256, 256>>>(o, ahi, alo);
    gemm_ts<<<ggrid, 256, GSMEM>>>(ahi, alo, whi + 3 * WS, wlo + 3 * WS, bo, out, 0);
}

// round 5
// speedup vs baseline: 2.8839x; 1.7595x over previous
#include <cuda_runtime.h>
#include <cuda_bf16.h>
#include <math.h>
#include <stdint.h>

// Problem constants
#define BB   4
#define TT   2048
#define EMB  1024
#define NH   16
#define HD   64
#define MM   (BB * TT)          // 8192 rows

// ---------------------------------------------------------------------------
// Scratch (device globals; no allocation allowed)
// ---------------------------------------------------------------------------
__device__ __nv_bfloat16 g_ahi[MM * EMB];          // A [8192][1024] (x, then attn out)
__device__ __nv_bfloat16 g_alo[MM * EMB];
__device__ __nv_bfloat16 g_whi[4 * EMB * EMB];     // W^T [N][K] per weight
__device__ __nv_bfloat16 g_wlo[4 * EMB * EMB];
__device__ __nv_bfloat16 g_qhi[MM * EMB];          // [b,h,t,d]
__device__ __nv_bfloat16 g_qlo[MM * EMB];
__device__ __nv_bfloat16 g_khi[MM * EMB];          // [b,h,t,d]
__device__ __nv_bfloat16 g_klo[MM * EMB];
__device__ __nv_bfloat16 g_vthi[MM * EMB];         // [b,h,d,t] (transposed)
__device__ __nv_bfloat16 g_vtlo[MM * EMB];

// ---------------------------------------------------------------------------
// Helpers (plain-sm_103-safe PTX: ldmatrix / mma.sync / cp.async)
// ---------------------------------------------------------------------------
__device__ __forceinline__ uint32_t smem_u32(const void* p) {
    uint32_t a;
    asm("{ .reg .u64 t; cvta.to.shared.u64 t, %1; cvt.u32.u64 %0, t; }"
        : "=r"(a) : "l"(p));
    return a;
}

#define LDSM_X4(R, addr) \
    asm volatile("ldmatrix.sync.aligned.m8n8.x4.shared.b16 {%0,%1,%2,%3}, [%4];" \
        : "=r"((R)[0]), "=r"((R)[1]), "=r"((R)[2]), "=r"((R)[3]) : "r"(addr))

#define MMA16816(C, A, B) \
    asm volatile("mma.sync.aligned.m16n8k16.row.col.f32.bf16.bf16.f32 " \
        "{%0,%1,%2,%3}, {%4,%5,%6,%7}, {%8,%9}, {%0,%1,%2,%3};" \
        : "+f"((C)[0]), "+f"((C)[1]), "+f"((C)[2]), "+f"((C)[3]) \
        : "r"((A)[0]), "r"((A)[1]), "r"((A)[2]), "r"((A)[3]), \
          "r"((B)[0]), "r"((B)[1]))

#define CP_ASYNC16(dst, src) \
    asm volatile("cp.async.cg.shared.global [%0], [%1], 16;" :: "r"(dst), "l"(src))
#define CP_COMMIT() asm volatile("cp.async.commit_group;")
#define CP_WAIT1()  asm volatile("cp.async.wait_group 1;")
#define CP_WAIT0()  asm volatile("cp.async.wait_group 0;")

__device__ __forceinline__ void split2(float x, float y, uint32_t& hp, uint32_t& lp) {
    __nv_bfloat16 hx = __float2bfloat16(x);
    __nv_bfloat16 hy = __float2bfloat16(y);
    __nv_bfloat16 lx = __float2bfloat16(x - __bfloat162float(hx));
    __nv_bfloat16 ly = __float2bfloat16(y - __bfloat162float(hy));
    __nv_bfloat162 h2 = __halves2bfloat162(hx, hy);
    __nv_bfloat162 l2 = __halves2bfloat162(lx, ly);
    hp = *(uint32_t*)&h2;
    lp = *(uint32_t*)&l2;
}

// ---------------------------------------------------------------------------
// split_x: fp32 [8192,1024] row-major -> hi/lo bf16 row-major
// ---------------------------------------------------------------------------
__global__ __launch_bounds__(256)
void split_x(const float* __restrict__ X, __nv_bfloat16* __restrict__ hi,
             __nv_bfloat16* __restrict__ lo)
{
    int idx = blockIdx.x * 256 + threadIdx.x;
    size_t e = (size_t)idx * 4;
    float4 v = *(const float4*)(X + e);
    uint2 hw, lw;
    split2(v.x, v.y, hw.x, lw.x);
    split2(v.z, v.w, hw.y, lw.y);
    *(uint2*)(hi + e) = hw;
    *(uint2*)(lo + e) = lw;
}

// ---------------------------------------------------------------------------
// split_wt: W [K,N] fp32 -> W^T [N,K] hi/lo bf16 (32x32 smem transpose)
// ---------------------------------------------------------------------------
__global__ __launch_bounds__(256)
void split_wt(const float* __restrict__ W, __nv_bfloat16* __restrict__ hi,
              __nv_bfloat16* __restrict__ lo)
{
    __shared__ float ts[32][33];
    const int n0 = blockIdx.x * 32, k0 = blockIdx.y * 32;
    const int tx = threadIdx.x, ty = threadIdx.y;

#pragma unroll
    for (int p = 0; p < 4; p++) {
        int ky = ty + p * 8;
        ts[ky][tx] = W[(size_t)(k0 + ky) * EMB + n0 + tx];
    }
    __syncthreads();
#pragma unroll
    for (int p = 0; p < 4; p++) {
        int ny = ty + p * 8;
        float v = ts[tx][ny];
        __nv_bfloat16 h = __float2bfloat16(v);
        __nv_bfloat16 l = __float2bfloat16(v - __bfloat162float(h));
        size_t off = (size_t)(n0 + ny) * EMB + k0 + tx;
        hi[off] = h;
        lo[off] = l;
    }
}

// ---------------------------------------------------------------------------
// Tensor-core GEMM via mma.sync (bf16 split, 3 terms).
// mode 0: C fp32 [M][N].  mode 1: Chi/Clo bf16 [b,h,t,d].  mode 2: [b,h,d,t].
// ---------------------------------------------------------------------------
#define TPAD  40
#define TSZ   (128 * TPAD)
#define GSMEM (2 * 4 * TSZ * 2)

__global__ __launch_bounds__(256)
void gemm_ts(const __nv_bfloat16* __restrict__ Ahi, const __nv_bfloat16* __restrict__ Alo,
             const __nv_bfloat16* __restrict__ Whi, const __nv_bfloat16* __restrict__ Wlo,
             const float* __restrict__ bias, float* __restrict__ C,
             __nv_bfloat16* __restrict__ Chi, __nv_bfloat16* __restrict__ Clo, int mode)
{
    extern __shared__ __align__(128) __nv_bfloat16 sm[];
    const uint32_t sbase = smem_u32(sm);
    const int tid  = threadIdx.x;
    const int lane = tid & 31;
    const int warp = tid >> 5;
    const int wm = warp >> 2;
    const int wn = warp & 3;
    const int n0 = blockIdx.x * 128;
    const int m0 = blockIdx.y * 128;

    const __nv_bfloat16* srcs[4] = {
        Ahi + (size_t)m0 * EMB, Alo + (size_t)m0 * EMB,
        Whi + (size_t)n0 * EMB, Wlo + (size_t)n0 * EMB
    };

    float acc[4][4][4] = {};

#define LOAD_STAGE(s, k0_)                                                    \
    do {                                                                      \
        _Pragma("unroll")                                                     \
        for (int p = 0; p < 8; p++) {                                         \
            int c = tid + p * 256;                                            \
            int t = c >> 9;                                                   \
            int r = (c >> 2) & 127;                                           \
            int c16 = c & 3;                                                  \
            uint32_t dst = sbase + (((s) * 4 + t) * TSZ + r * TPAD + c16 * 8) * 2; \
            const void* src = srcs[t] + (size_t)r * EMB + (k0_) + c16 * 8;    \
            CP_ASYNC16(dst, src);                                             \
        }                                                                     \
        CP_COMMIT();                                                          \
    } while (0)

    LOAD_STAGE(0, 0);

    const int arow_in = (lane & 7) + ((lane >> 3) & 1) * 8;
    const int ak_half = (lane >> 4) * 8;
    const int bg      = lane >> 3;
    const int brow_in = (lane & 7) + ((bg >> 1) & 1) * 8;
    const int bk_half = (bg & 1) * 8;

    for (int kt = 0; kt < 32; kt++) {
        const int s = kt & 1;
        if (kt < 31) {
            LOAD_STAGE(s ^ 1, (kt + 1) * 32);
            CP_WAIT1();
        } else {
            CP_WAIT0();
        }
        __syncthreads();

        const uint32_t st = sbase + s * 4 * TSZ * 2;
#pragma unroll
        for (int kc = 0; kc < 32; kc += 16) {
            uint32_t ah[4][4], al[4][4], bh[4][2], bl[4][2];
#pragma unroll
            for (int i = 0; i < 4; i++) {
                int row = wm * 64 + i * 16 + arow_in;
                uint32_t addr = st + (row * TPAD + kc + ak_half) * 2;
                LDSM_X4(ah[i], addr);
                LDSM_X4(al[i], addr + TSZ * 2);
            }
#pragma unroll
            for (int j = 0; j < 2; j++) {
                int nrow = wn * 32 + j * 16 + brow_in;
                uint32_t addr = st + (2 * TSZ + nrow * TPAD + kc + bk_half) * 2;
                uint32_t r4[4];
                LDSM_X4(r4, addr);
                bh[2 * j][0] = r4[0]; bh[2 * j][1] = r4[1];
                bh[2 * j + 1][0] = r4[2]; bh[2 * j + 1][1] = r4[3];
                LDSM_X4(r4, addr + TSZ * 2);
                bl[2 * j][0] = r4[0]; bl[2 * j][1] = r4[1];
                bl[2 * j + 1][0] = r4[2]; bl[2 * j + 1][1] = r4[3];
            }
#pragma unroll
            for (int i = 0; i < 4; i++)
#pragma unroll
                for (int j = 0; j < 4; j++) {
                    MMA16816(acc[i][j], ah[i], bh[j]);
                    MMA16816(acc[i][j], ah[i], bl[j]);
                    MMA16816(acc[i][j], al[i], bh[j]);
                }
        }
        __syncthreads();
    }

    // ---- epilogue ----
    const int ln4 = lane >> 2;
    const int lm4 = lane & 3;
#pragma unroll
    for (int j = 0; j < 4; j++) {
        int n = n0 + wn * 32 + j * 8 + lm4 * 2;
        float2 bj = *(const float2*)(bias + n);
        int hh = n >> 6;
        int d  = n & 63;
#pragma unroll
        for (int i = 0; i < 4; i++) {
#pragma unroll
            for (int half = 0; half < 2; half++) {
                int m = m0 + wm * 64 + i * 16 + ln4 + half * 8;
                float rx = acc[i][j][half * 2 + 0] + bj.x;
                float ry = acc[i][j][half * 2 + 1] + bj.y;
                if (mode == 0) {
                    float2 res = make_float2(rx, ry);
                    *(float2*)(C + (size_t)m * EMB + n) = res;
                } else {
                    int b = m >> 11;
                    int t = m & (TT - 1);
                    uint32_t hp, lp;
                    split2(rx, ry, hp, lp);
                    if (mode == 1) {
                        size_t idx = (((size_t)(b * NH + hh) * TT + t) * HD) + d;
                        *(uint32_t*)(Chi + idx) = hp;
                        *(uint32_t*)(Clo + idx) = lp;
                    } else {
                        size_t idx = (((size_t)(b * NH + hh) * HD + d) * TT) + t;
                        __nv_bfloat162 h2 = *(__nv_bfloat162*)&hp;
                        __nv_bfloat162 l2 = *(__nv_bfloat162*)&lp;
                        Chi[idx]      = __low2bfloat16(h2);
                        Chi[idx + TT] = __high2bfloat16(h2);
                        Clo[idx]      = __low2bfloat16(l2);
                        Clo[idx + TT] = __high2bfloat16(l2);
                    }
                }
            }
        }
    }
}

// ---------------------------------------------------------------------------
// Tensor-core causal flash attention (bf16 split, 3 terms each gemm).
// CTA: 128 q-rows x 64-key chunks. 8 warps, 16 rows each.
// Writes normalized output as hi/lo bf16 into the final GEMM's A buffers.
// ---------------------------------------------------------------------------
#define TP    72
#define QTSZ  (128 * TP)
#define KTSZ  (64 * TP)
#define ASMEM ((2 * QTSZ + 8 * KTSZ) * 2)   // 110592 bytes

__global__ __launch_bounds__(256, 1)
void attn_tc(const __nv_bfloat16* __restrict__ Qh, const __nv_bfloat16* __restrict__ Ql,
             const __nv_bfloat16* __restrict__ Kh, const __nv_bfloat16* __restrict__ Kl,
             const __nv_bfloat16* __restrict__ Vh, const __nv_bfloat16* __restrict__ Vl,
             __nv_bfloat16* __restrict__ Oh, __nv_bfloat16* __restrict__ Ol)
{
    extern __shared__ __align__(128) __nv_bfloat16 smb[];
    const uint32_t sb = smem_u32(smb);
    const int tid = threadIdx.x, lane = tid & 31, w = tid >> 5;
    const int qt = gridDim.x - 1 - blockIdx.x;
    const int h = blockIdx.y, b = blockIdx.z;
    const int bh = b * NH + h;
    const size_t kbase = (size_t)bh * TT * HD;   // Q/K [t][d]
    const size_t vbase = (size_t)bh * HD * TT;   // V^T [d][t]
    const int nch = 2 * qt + 2;

    // ---- Q tiles (hi, lo) ----
    {
#pragma unroll
        for (int p = 0; p < 8; p++) {
            int c = tid + p * 256;
            int tl = c >> 10, row = (c >> 3) & 127, c16 = c & 7;
            uint32_t dst = sb + ((tl ? QTSZ : 0) + row * TP + c16 * 8) * 2;
            const __nv_bfloat16* src =
                (tl ? Ql : Qh) + kbase + (size_t)(128 * qt + row) * HD + c16 * 8;
            CP_ASYNC16(dst, src);
        }
        CP_COMMIT();
    }

#define LOADKV(s, jc_)                                                          \
    do {                                                                        \
        _Pragma("unroll")                                                       \
        for (int p = 0; p < 8; p++) {                                           \
            int c = tid + p * 256;                                              \
            int tl = c >> 9, row = (c >> 3) & 63, c16 = c & 7;                  \
            uint32_t dst = sb + (2 * QTSZ + (s) * 4 * KTSZ + tl * KTSZ          \
                                 + row * TP + c16 * 8) * 2;                     \
            const __nv_bfloat16* src;                                           \
            if (tl == 0)                                                        \
                src = Kh + kbase + (size_t)(64 * (jc_) + row) * HD + c16 * 8;   \
            else if (tl == 1)                                                   \
                src = Kl + kbase + (size_t)(64 * (jc_) + row) * HD + c16 * 8;   \
            else if (tl == 2)                                                   \
                src = Vh + vbase + (size_t)row * TT + 64 * (jc_) + c16 * 8;     \
            else                                                                \
                src = Vl + vbase + (size_t)row * TT + 64 * (jc_) + c16 * 8;     \
            CP_ASYNC16(dst, src);                                               \
        }                                                                       \
        CP_COMMIT();                                                            \
    } while (0)

    LOADKV(0, 0);
    CP_WAIT1();              // Q group done
    __syncthreads();

    const int arow_in = (lane & 7) + ((lane >> 3) & 1) * 8;
    const int ak_half = (lane >> 4) * 8;
    const int bg      = lane >> 3;
    const int brow_in = (lane & 7) + ((bg >> 1) & 1) * 8;
    const int bk_half = (bg & 1) * 8;

    // preload Q fragments (constant across key loop)
    uint32_t qh[4][4], ql[4][4];
    {
        int qrow = 16 * w + arow_in;
#pragma unroll
        for (int kt = 0; kt < 4; kt++) {
            uint32_t addr = sb + (qrow * TP + 16 * kt + ak_half) * 2;
            LDSM_X4(qh[kt], addr);
            LDSM_X4(ql[kt], addr + QTSZ * 2);
        }
    }

    const int r0 = lane >> 2;
    const int c0 = 2 * (lane & 3);
    float m0s = -1e30f, m1s = -1e30f, l0s = 0.0f, l1s = 0.0f;
    float o[8][4] = {};

    for (int jc = 0; jc < nch; jc++) {
        const int s = jc & 1;
        if (jc + 1 < nch) { LOADKV(s ^ 1, jc + 1); CP_WAIT1(); }
        else              { CP_WAIT0(); }
        __syncthreads();

        const uint32_t stb = sb + (2 * QTSZ + s * 4 * KTSZ) * 2;

        // ---- S = Q K^T (3-term) ----
        float sa[8][4] = {};
#pragma unroll
        for (int kt = 0; kt < 4; kt++) {
#pragma unroll
            for (int jt = 0; jt < 4; jt++) {
                uint32_t kh4[4], kl4[4];
                uint32_t addr = stb + ((16 * jt + brow_in) * TP + 16 * kt + bk_half) * 2;
                LDSM_X4(kh4, addr);
                LDSM_X4(kl4, addr + KTSZ * 2);
                MMA16816(sa[2 * jt],     qh[kt], kh4);
                MMA16816(sa[2 * jt],     ql[kt], kh4);
                MMA16816(sa[2 * jt],     qh[kt], kl4);
                MMA16816(sa[2 * jt + 1], qh[kt], kh4 + 2);
                MMA16816(sa[2 * jt + 1], ql[kt], kh4 + 2);
                MMA16816(sa[2 * jt + 1], qh[kt], kl4 + 2);
            }
        }

        // ---- scale + causal mask ----
#pragma unroll
        for (int j = 0; j < 8; j++)
#pragma unroll
            for (int rg = 0; rg < 4; rg++) sa[j][rg] *= 0.125f;

        if (jc >= nch - 2) {
            int q0 = 128 * qt + 16 * w + r0;
            int k0 = 64 * jc;
#pragma unroll
            for (int j = 0; j < 8; j++) {
                int key = k0 + 8 * j + c0;
                if (key     > q0)     sa[j][0] = -1e30f;
                if (key + 1 > q0)     sa[j][1] = -1e30f;
                if (key     > q0 + 8) sa[j][2] = -1e30f;
                if (key + 1 > q0 + 8) sa[j][3] = -1e30f;
            }
        }

        // ---- online softmax ----
        float mx0 = sa[0][0], mx1 = sa[0][2];
#pragma unroll
        for (int j = 0; j < 8; j++) {
            mx0 = fmaxf(mx0, fmaxf(sa[j][0], sa[j][1]));
            mx1 = fmaxf(mx1, fmaxf(sa[j][2], sa[j][3]));
        }
        mx0 = fmaxf(mx0, __shfl_xor_sync(0xffffffffu, mx0, 1));
        mx0 = fmaxf(mx0, __shfl_xor_sync(0xffffffffu, mx0, 2));
        mx1 = fmaxf(mx1, __shfl_xor_sync(0xffffffffu, mx1, 1));
        mx1 = fmaxf(mx1, __shfl_xor_sync(0xffffffffu, mx1, 2));
        float mn0 = fmaxf(m0s, mx0), mn1 = fmaxf(m1s, mx1);
        float al0 = __expf(m0s - mn0), al1 = __expf(m1s - mn1);
        m0s = mn0; m1s = mn1;
        float sum0 = 0.0f, sum1 = 0.0f;
#pragma unroll
        for (int j = 0; j < 8; j++) {
            sa[j][0] = __expf(sa[j][0] - mn0); sum0 += sa[j][0];
            sa[j][1] = __expf(sa[j][1] - mn0); sum0 += sa[j][1];
            sa[j][2] = __expf(sa[j][2] - mn1); sum1 += sa[j][2];
            sa[j][3] = __expf(sa[j][3] - mn1); sum1 += sa[j][3];
        }
        sum0 += __shfl_xor_sync(0xffffffffu, sum0, 1);
        sum0 += __shfl_xor_sync(0xffffffffu, sum0, 2);
        sum1 += __shfl_xor_sync(0xffffffffu, sum1, 1);
        sum1 += __shfl_xor_sync(0xffffffffu, sum1, 2);
        l0s = l0s * al0 + sum0;
        l1s = l1s * al1 + sum1;
#pragma unroll
        for (int j = 0; j < 8; j++) {
            o[j][0] *= al0; o[j][1] *= al0;
            o[j][2] *= al1; o[j][3] *= al1;
        }

        // ---- pack P into A-fragments (hi/lo) ----
        uint32_t ph[4][4], pl[4][4];
#pragma unroll
        for (int kt = 0; kt < 4; kt++) {
#pragma unroll
            for (int q2 = 0; q2 < 4; q2++) {
                int j  = 2 * kt + (q2 >> 1);
                int rg = (q2 & 1) * 2;
                split2(sa[j][rg], sa[j][rg + 1], ph[kt][q2], pl[kt][q2]);
            }
        }

        // ---- O += P V (3-term) ----
#pragma unroll
        for (int kt = 0; kt < 4; kt++) {
#pragma unroll
            for (int jt = 0; jt < 4; jt++) {
                uint32_t vh4[4], vl4[4];
                uint32_t addr = stb + (2 * KTSZ + (16 * jt + brow_in) * TP
                                       + 16 * kt + bk_half) * 2;
                LDSM_X4(vh4, addr);
                LDSM_X4(vl4, addr + KTSZ * 2);
                MMA16816(o[2 * jt],     ph[kt], vh4);
                MMA16816(o[2 * jt],     pl[kt], vh4);
                MMA16816(o[2 * jt],     ph[kt], vl4);
                MMA16816(o[2 * jt + 1], ph[kt], vh4 + 2);
                MMA16816(o[2 * jt + 1], pl[kt], vh4 + 2);
                MMA16816(o[2 * jt + 1], ph[kt], vl4 + 2);
            }
        }
        __syncthreads();
    }

    // ---- epilogue: normalize, split, store as next GEMM's A ----
    float inv0 = 1.0f / l0s, inv1 = 1.0f / l1s;
    int t0 = 128 * qt + 16 * w + r0;
#pragma unroll
    for (int j = 0; j < 8; j++) {
        int e = h * 64 + 8 * j + c0;
        uint32_t hp, lp;
        split2(o[j][0] * inv0, o[j][1] * inv0, hp, lp);
        size_t idx0 = (size_t)(b * TT + t0) * EMB + e;
        *(uint32_t*)(Oh + idx0) = hp;
        *(uint32_t*)(Ol + idx0) = lp;
        split2(o[j][2] * inv1, o[j][3] * inv1, hp, lp);
        size_t idx1 = (size_t)(b * TT + t0 + 8) * EMB + e;
        *(uint32_t*)(Oh + idx1) = hp;
        *(uint32_t*)(Ol + idx1) = lp;
    }
}

// ---------------------------------------------------------------------------
// Launch
// ---------------------------------------------------------------------------
extern "C" void kernel_launch(void* const* d_in, const int* in_sizes, int n_in,
                              void* d_out, int out_size)
{
    const float* x  = (const float*)d_in[0];
    const float* Wq = (const float*)d_in[1];
    const float* bq = (const float*)d_in[2];
    const float* Wk = (const float*)d_in[3];
    const float* bk = (const float*)d_in[4];
    const float* Wv = (const float*)d_in[5];
    const float* bv = (const float*)d_in[6];
    const float* Wo = (const float*)d_in[7];
    const float* bo = (const float*)d_in[8];
    float* out = (float*)d_out;

    __nv_bfloat16 *ahi, *alo, *whi, *wlo, *qhi, *qlo, *khi, *klo, *vthi, *vtlo;
    cudaGetSymbolAddress((void**)&ahi, g_ahi);
    cudaGetSymbolAddress((void**)&alo, g_alo);
    cudaGetSymbolAddress((void**)&whi, g_whi);
    cudaGetSymbolAddress((void**)&wlo, g_wlo);
    cudaGetSymbolAddress((void**)&qhi, g_qhi);
    cudaGetSymbolAddress((void**)&qlo, g_qlo);
    cudaGetSymbolAddress((void**)&khi, g_khi);
    cudaGetSymbolAddress((void**)&klo, g_klo);
    cudaGetSymbolAddress((void**)&vthi, g_vthi);
    cudaGetSymbolAddress((void**)&vtlo, g_vtlo);

    cudaFuncSetAttribute(gemm_ts, cudaFuncAttributeMaxDynamicSharedMemorySize, GSMEM);
    cudaFuncSetAttribute(attn_tc, cudaFuncAttributeMaxDynamicSharedMemorySize, ASMEM);

    const size_t WS = (size_t)EMB * EMB;

    // Split inputs
    split_x<<<(MM * EMB / 4) / 256, 256>>>(x, ahi, alo);
    dim3 wt_grid(EMB / 32, EMB / 32);
    dim3 wt_blk(32, 8);
    split_wt<<<wt_grid, wt_blk>>>(Wq, whi + 0 * WS, wlo + 0 * WS);
    split_wt<<<wt_grid, wt_blk>>>(Wk, whi + 1 * WS, wlo + 1 * WS);
    split_wt<<<wt_grid, wt_blk>>>(Wv, whi + 2 * WS, wlo + 2 * WS);
    split_wt<<<wt_grid, wt_blk>>>(Wo, whi + 3 * WS, wlo + 3 * WS);

    // QKV projections -> bf16 hi/lo operands for attention
    dim3 ggrid(EMB / 128, MM / 128);    // (8, 64)
    gemm_ts<<<ggrid, 256, GSMEM>>>(ahi, alo, whi + 0 * WS, wlo + 0 * WS, bq,
                                   nullptr, qhi, qlo, 1);
    gemm_ts<<<ggrid, 256, GSMEM>>>(ahi, alo, whi + 1 * WS, wlo + 1 * WS, bk,
                                   nullptr, khi, klo, 1);
    gemm_ts<<<ggrid, 256, GSMEM>>>(ahi, alo, whi + 2 * WS, wlo + 2 * WS, bv,
                                   nullptr, vthi, vtlo, 2);

    // Attention on tensor cores -> writes ahi/alo (A of final GEMM)
    dim3 attn_grid(TT / 128, NH, BB);   // (16, 16, 4)
    attn_tc<<<attn_grid, 256, ASMEM>>>(qhi, qlo, khi, klo, vthi, vtlo, ahi, alo);

    // Output projection (fp32 out)
    gemm_ts<<<ggrid, 256, GSMEM>>>(ahi, alo, whi + 3 * WS, wlo + 3 * WS, bo,
                                   out, nullptr, nullptr, 0);
}

// round 6
// speedup vs baseline: 2.9094x; 1.0089x over previous
#include <cuda_runtime.h>
#include <cuda_bf16.h>
#include <math.h>
#include <stdint.h>

// Problem constants
#define BB   4
#define TT   2048
#define EMB  1024
#define NH   16
#define HD   64
#define MM   (BB * TT)          // 8192 rows

// ---------------------------------------------------------------------------
// Scratch (device globals; no allocation allowed)
// ---------------------------------------------------------------------------
__device__ __nv_bfloat16 g_ahi[MM * EMB];          // A [8192][1024] (x, then attn out)
__device__ __nv_bfloat16 g_alo[MM * EMB];
__device__ __nv_bfloat16 g_whi[4 * EMB * EMB];     // W^T [N][K] per weight
__device__ __nv_bfloat16 g_wlo[4 * EMB * EMB];
__device__ __nv_bfloat16 g_qhi[MM * EMB];          // [b,h,t,d]
__device__ __nv_bfloat16 g_qlo[MM * EMB];
__device__ __nv_bfloat16 g_khi[MM * EMB];          // [b,h,t,d]
__device__ __nv_bfloat16 g_klo[MM * EMB];
__device__ __nv_bfloat16 g_vthi[MM * EMB];         // [b,h,d,t] (transposed)
__device__ __nv_bfloat16 g_vtlo[MM * EMB];

// ---------------------------------------------------------------------------
// Helpers (plain-sm_103-safe PTX: ldmatrix / mma.sync / cp.async)
// ---------------------------------------------------------------------------
__device__ __forceinline__ uint32_t smem_u32(const void* p) {
    uint32_t a;
    asm("{ .reg .u64 t; cvta.to.shared.u64 t, %1; cvt.u32.u64 %0, t; }"
        : "=r"(a) : "l"(p));
    return a;
}

__device__ __forceinline__ float ex2(float x) {
    float r;
    asm("ex2.approx.ftz.f32 %0, %1;" : "=f"(r) : "f"(x));
    return r;
}

#define LDSM_X4(R, addr) \
    asm volatile("ldmatrix.sync.aligned.m8n8.x4.shared.b16 {%0,%1,%2,%3}, [%4];" \
        : "=r"((R)[0]), "=r"((R)[1]), "=r"((R)[2]), "=r"((R)[3]) : "r"(addr))

#define MMA16816(C, A, B) \
    asm volatile("mma.sync.aligned.m16n8k16.row.col.f32.bf16.bf16.f32 " \
        "{%0,%1,%2,%3}, {%4,%5,%6,%7}, {%8,%9}, {%0,%1,%2,%3};" \
        : "+f"((C)[0]), "+f"((C)[1]), "+f"((C)[2]), "+f"((C)[3]) \
        : "r"((A)[0]), "r"((A)[1]), "r"((A)[2]), "r"((A)[3]), \
          "r"((B)[0]), "r"((B)[1]))

#define CP_ASYNC16(dst, src) \
    asm volatile("cp.async.cg.shared.global [%0], [%1], 16;" :: "r"(dst), "l"(src))
#define CP_COMMIT() asm volatile("cp.async.commit_group;")
#define CP_WAIT1()  asm volatile("cp.async.wait_group 1;")
#define CP_WAIT0()  asm volatile("cp.async.wait_group 0;")

__device__ __forceinline__ void split2(float x, float y, uint32_t& hp, uint32_t& lp) {
    __nv_bfloat16 hx = __float2bfloat16(x);
    __nv_bfloat16 hy = __float2bfloat16(y);
    __nv_bfloat16 lx = __float2bfloat16(x - __bfloat162float(hx));
    __nv_bfloat16 ly = __float2bfloat16(y - __bfloat162float(hy));
    __nv_bfloat162 h2 = __halves2bfloat162(hx, hy);
    __nv_bfloat162 l2 = __halves2bfloat162(lx, ly);
    hp = *(uint32_t*)&h2;
    lp = *(uint32_t*)&l2;
}

// ---------------------------------------------------------------------------
// split_x: fp32 [8192,1024] row-major -> hi/lo bf16 row-major
// ---------------------------------------------------------------------------
__global__ __launch_bounds__(256)
void split_x(const float* __restrict__ X, __nv_bfloat16* __restrict__ hi,
             __nv_bfloat16* __restrict__ lo)
{
    int idx = blockIdx.x * 256 + threadIdx.x;
    size_t e = (size_t)idx * 4;
    float4 v = *(const float4*)(X + e);
    uint2 hw, lw;
    split2(v.x, v.y, hw.x, lw.x);
    split2(v.z, v.w, hw.y, lw.y);
    *(uint2*)(hi + e) = hw;
    *(uint2*)(lo + e) = lw;
}

// ---------------------------------------------------------------------------
// split_wt: W [K,N] fp32 -> W^T [N,K] hi/lo bf16 (32x32 smem transpose)
// ---------------------------------------------------------------------------
__global__ __launch_bounds__(256)
void split_wt(const float* __restrict__ W, __nv_bfloat16* __restrict__ hi,
              __nv_bfloat16* __restrict__ lo)
{
    __shared__ float ts[32][33];
    const int n0 = blockIdx.x * 32, k0 = blockIdx.y * 32;
    const int tx = threadIdx.x, ty = threadIdx.y;

#pragma unroll
    for (int p = 0; p < 4; p++) {
        int ky = ty + p * 8;
        ts[ky][tx] = W[(size_t)(k0 + ky) * EMB + n0 + tx];
    }
    __syncthreads();
#pragma unroll
    for (int p = 0; p < 4; p++) {
        int ny = ty + p * 8;
        float v = ts[tx][ny];
        __nv_bfloat16 h = __float2bfloat16(v);
        __nv_bfloat16 l = __float2bfloat16(v - __bfloat162float(h));
        size_t off = (size_t)(n0 + ny) * EMB + k0 + tx;
        hi[off] = h;
        lo[off] = l;
    }
}

// ---------------------------------------------------------------------------
// Tensor-core GEMM via mma.sync (bf16 split, 3 terms).
// mode 0: C fp32 [M][N].  mode 1: Chi/Clo bf16 [b,h,t,d].  mode 2: [b,h,d,t].
// ---------------------------------------------------------------------------
#define TPAD  40
#define TSZ   (128 * TPAD)
#define GSMEM (2 * 4 * TSZ * 2)

__global__ __launch_bounds__(256)
void gemm_ts(const __nv_bfloat16* __restrict__ Ahi, const __nv_bfloat16* __restrict__ Alo,
             const __nv_bfloat16* __restrict__ Whi, const __nv_bfloat16* __restrict__ Wlo,
             const float* __restrict__ bias, float* __restrict__ C,
             __nv_bfloat16* __restrict__ Chi, __nv_bfloat16* __restrict__ Clo, int mode)
{
    extern __shared__ __align__(128) __nv_bfloat16 sm[];
    const uint32_t sbase = smem_u32(sm);
    const int tid  = threadIdx.x;
    const int lane = tid & 31;
    const int warp = tid >> 5;
    const int wm = warp >> 2;
    const int wn = warp & 3;
    const int n0 = blockIdx.x * 128;
    const int m0 = blockIdx.y * 128;

    const __nv_bfloat16* srcs[4] = {
        Ahi + (size_t)m0 * EMB, Alo + (size_t)m0 * EMB,
        Whi + (size_t)n0 * EMB, Wlo + (size_t)n0 * EMB
    };

    float acc[4][4][4] = {};

#define LOAD_STAGE(s, k0_)                                                    \
    do {                                                                      \
        _Pragma("unroll")                                                     \
        for (int p = 0; p < 8; p++) {                                         \
            int c = tid + p * 256;                                            \
            int t = c >> 9;                                                   \
            int r = (c >> 2) & 127;                                           \
            int c16 = c & 3;                                                  \
            uint32_t dst = sbase + (((s) * 4 + t) * TSZ + r * TPAD + c16 * 8) * 2; \
            const void* src = srcs[t] + (size_t)r * EMB + (k0_) + c16 * 8;    \
            CP_ASYNC16(dst, src);                                             \
        }                                                                     \
        CP_COMMIT();                                                          \
    } while (0)

    LOAD_STAGE(0, 0);

    const int arow_in = (lane & 7) + ((lane >> 3) & 1) * 8;
    const int ak_half = (lane >> 4) * 8;
    const int bg      = lane >> 3;
    const int brow_in = (lane & 7) + ((bg >> 1) & 1) * 8;
    const int bk_half = (bg & 1) * 8;

    for (int kt = 0; kt < 32; kt++) {
        const int s = kt & 1;
        if (kt < 31) {
            LOAD_STAGE(s ^ 1, (kt + 1) * 32);
            CP_WAIT1();
        } else {
            CP_WAIT0();
        }
        __syncthreads();

        const uint32_t st = sbase + s * 4 * TSZ * 2;
#pragma unroll
        for (int kc = 0; kc < 32; kc += 16) {
            uint32_t ah[4][4], al[4][4], bh[4][2], bl[4][2];
#pragma unroll
            for (int i = 0; i < 4; i++) {
                int row = wm * 64 + i * 16 + arow_in;
                uint32_t addr = st + (row * TPAD + kc + ak_half) * 2;
                LDSM_X4(ah[i], addr);
                LDSM_X4(al[i], addr + TSZ * 2);
            }
#pragma unroll
            for (int j = 0; j < 2; j++) {
                int nrow = wn * 32 + j * 16 + brow_in;
                uint32_t addr = st + (2 * TSZ + nrow * TPAD + kc + bk_half) * 2;
                uint32_t r4[4];
                LDSM_X4(r4, addr);
                bh[2 * j][0] = r4[0]; bh[2 * j][1] = r4[1];
                bh[2 * j + 1][0] = r4[2]; bh[2 * j + 1][1] = r4[3];
                LDSM_X4(r4, addr + TSZ * 2);
                bl[2 * j][0] = r4[0]; bl[2 * j][1] = r4[1];
                bl[2 * j + 1][0] = r4[2]; bl[2 * j + 1][1] = r4[3];
            }
#pragma unroll
            for (int i = 0; i < 4; i++)
#pragma unroll
                for (int j = 0; j < 4; j++) {
                    MMA16816(acc[i][j], ah[i], bh[j]);
                    MMA16816(acc[i][j], ah[i], bl[j]);
                    MMA16816(acc[i][j], al[i], bh[j]);
                }
        }
        __syncthreads();
    }

    // ---- epilogue ----
    const int ln4 = lane >> 2;
    const int lm4 = lane & 3;
#pragma unroll
    for (int j = 0; j < 4; j++) {
        int n = n0 + wn * 32 + j * 8 + lm4 * 2;
        float2 bj = *(const float2*)(bias + n);
        int hh = n >> 6;
        int d  = n & 63;
#pragma unroll
        for (int i = 0; i < 4; i++) {
#pragma unroll
            for (int half = 0; half < 2; half++) {
                int m = m0 + wm * 64 + i * 16 + ln4 + half * 8;
                float rx = acc[i][j][half * 2 + 0] + bj.x;
                float ry = acc[i][j][half * 2 + 1] + bj.y;
                if (mode == 0) {
                    float2 res = make_float2(rx, ry);
                    *(float2*)(C + (size_t)m * EMB + n) = res;
                } else {
                    int b = m >> 11;
                    int t = m & (TT - 1);
                    uint32_t hp, lp;
                    split2(rx, ry, hp, lp);
                    if (mode == 1) {
                        size_t idx = (((size_t)(b * NH + hh) * TT + t) * HD) + d;
                        *(uint32_t*)(Chi + idx) = hp;
                        *(uint32_t*)(Clo + idx) = lp;
                    } else {
                        size_t idx = (((size_t)(b * NH + hh) * HD + d) * TT) + t;
                        __nv_bfloat162 h2 = *(__nv_bfloat162*)&hp;
                        __nv_bfloat162 l2 = *(__nv_bfloat162*)&lp;
                        Chi[idx]      = __low2bfloat16(h2);
                        Chi[idx + TT] = __high2bfloat16(h2);
                        Clo[idx]      = __low2bfloat16(l2);
                        Clo[idx + TT] = __high2bfloat16(l2);
                    }
                }
            }
        }
    }
}

// ---------------------------------------------------------------------------
// Tensor-core causal flash attention (bf16 split, 3 terms each gemm).
// CTA: 128 q-rows x 64-key chunks. 8 warps, 16 rows each.
// Q stays resident in smem; fragments re-ldmatrix'd per chunk (reg pressure).
// 2 CTAs/SM target.
// ---------------------------------------------------------------------------
#define TP    72
#define QTSZ  (128 * TP)
#define KTSZ  (64 * TP)
#define ASMEM ((2 * QTSZ + 8 * KTSZ) * 2)   // 110592 bytes

#define SCALE2 0.180336880f   // 0.125 * log2(e)

__global__ __launch_bounds__(256, 2)
void attn_tc(const __nv_bfloat16* __restrict__ Qh, const __nv_bfloat16* __restrict__ Ql,
             const __nv_bfloat16* __restrict__ Kh, const __nv_bfloat16* __restrict__ Kl,
             const __nv_bfloat16* __restrict__ Vh, const __nv_bfloat16* __restrict__ Vl,
             __nv_bfloat16* __restrict__ Oh, __nv_bfloat16* __restrict__ Ol)
{
    extern __shared__ __align__(128) __nv_bfloat16 smb[];
    const uint32_t sb = smem_u32(smb);
    const int tid = threadIdx.x, lane = tid & 31, w = tid >> 5;
    const int qt = gridDim.x - 1 - blockIdx.x;
    const int h = blockIdx.y, b = blockIdx.z;
    const int bh = b * NH + h;
    const size_t kbase = (size_t)bh * TT * HD;   // Q/K [t][d]
    const size_t vbase = (size_t)bh * HD * TT;   // V^T [d][t]
    const int nch = 2 * qt + 2;

    // ---- Q tiles (hi, lo) ----
    {
#pragma unroll
        for (int p = 0; p < 8; p++) {
            int c = tid + p * 256;
            int tl = c >> 10, row = (c >> 3) & 127, c16 = c & 7;
            uint32_t dst = sb + ((tl ? QTSZ : 0) + row * TP + c16 * 8) * 2;
            const __nv_bfloat16* src =
                (tl ? Ql : Qh) + kbase + (size_t)(128 * qt + row) * HD + c16 * 8;
            CP_ASYNC16(dst, src);
        }
        CP_COMMIT();
    }

#define LOADKV(s, jc_)                                                          \
    do {                                                                        \
        _Pragma("unroll")                                                       \
        for (int p = 0; p < 8; p++) {                                           \
            int c = tid + p * 256;                                              \
            int tl = c >> 9, row = (c >> 3) & 63, c16 = c & 7;                  \
            uint32_t dst = sb + (2 * QTSZ + (s) * 4 * KTSZ + tl * KTSZ          \
                                 + row * TP + c16 * 8) * 2;                     \
            const __nv_bfloat16* src;                                           \
            if (tl == 0)                                                        \
                src = Kh + kbase + (size_t)(64 * (jc_) + row) * HD + c16 * 8;   \
            else if (tl == 1)                                                   \
                src = Kl + kbase + (size_t)(64 * (jc_) + row) * HD + c16 * 8;   \
            else if (tl == 2)                                                   \
                src = Vh + vbase + (size_t)row * TT + 64 * (jc_) + c16 * 8;     \
            else                                                                \
                src = Vl + vbase + (size_t)row * TT + 64 * (jc_) + c16 * 8;     \
            CP_ASYNC16(dst, src);                                               \
        }                                                                       \
        CP_COMMIT();                                                            \
    } while (0)

    LOADKV(0, 0);
    CP_WAIT1();              // Q group done
    __syncthreads();

    const int arow_in = (lane & 7) + ((lane >> 3) & 1) * 8;
    const int ak_half = (lane >> 4) * 8;
    const int bg      = lane >> 3;
    const int brow_in = (lane & 7) + ((bg >> 1) & 1) * 8;
    const int bk_half = (bg & 1) * 8;

    const int r0 = lane >> 2;
    const int c0 = 2 * (lane & 3);
    float m0s = -1e30f, m1s = -1e30f, l0s = 0.0f, l1s = 0.0f;
    float o[8][4] = {};

    for (int jc = 0; jc < nch; jc++) {
        const int s = jc & 1;
        if (jc + 1 < nch) { LOADKV(s ^ 1, jc + 1); CP_WAIT1(); }
        else              { CP_WAIT0(); }
        __syncthreads();

        const uint32_t stb = sb + (2 * QTSZ + s * 4 * KTSZ) * 2;

        // ---- S = Q K^T (3-term); Q fragments re-loaded from resident smem ----
        float sa[8][4] = {};
#pragma unroll
        for (int kt = 0; kt < 4; kt++) {
            uint32_t qh4[4], ql4[4];
            {
                uint32_t qaddr = sb + ((16 * w + arow_in) * TP + 16 * kt + ak_half) * 2;
                LDSM_X4(qh4, qaddr);
                LDSM_X4(ql4, qaddr + QTSZ * 2);
            }
#pragma unroll
            for (int jt = 0; jt < 4; jt++) {
                uint32_t kh4[4], kl4[4];
                uint32_t addr = stb + ((16 * jt + brow_in) * TP + 16 * kt + bk_half) * 2;
                LDSM_X4(kh4, addr);
                LDSM_X4(kl4, addr + KTSZ * 2);
                MMA16816(sa[2 * jt],     qh4, kh4);
                MMA16816(sa[2 * jt],     ql4, kh4);
                MMA16816(sa[2 * jt],     qh4, kl4);
                MMA16816(sa[2 * jt + 1], qh4, kh4 + 2);
                MMA16816(sa[2 * jt + 1], ql4, kh4 + 2);
                MMA16816(sa[2 * jt + 1], qh4, kl4 + 2);
            }
        }

        // ---- scale (exp2 domain) + causal mask ----
#pragma unroll
        for (int j = 0; j < 8; j++)
#pragma unroll
            for (int rg = 0; rg < 4; rg++) sa[j][rg] *= SCALE2;

        if (jc >= nch - 2) {
            int q0 = 128 * qt + 16 * w + r0;
            int k0 = 64 * jc;
#pragma unroll
            for (int j = 0; j < 8; j++) {
                int key = k0 + 8 * j + c0;
                if (key     > q0)     sa[j][0] = -1e30f;
                if (key + 1 > q0)     sa[j][1] = -1e30f;
                if (key     > q0 + 8) sa[j][2] = -1e30f;
                if (key + 1 > q0 + 8) sa[j][3] = -1e30f;
            }
        }

        // ---- online softmax (base-2) ----
        float mx0 = sa[0][0], mx1 = sa[0][2];
#pragma unroll
        for (int j = 0; j < 8; j++) {
            mx0 = fmaxf(mx0, fmaxf(sa[j][0], sa[j][1]));
            mx1 = fmaxf(mx1, fmaxf(sa[j][2], sa[j][3]));
        }
        mx0 = fmaxf(mx0, __shfl_xor_sync(0xffffffffu, mx0, 1));
        mx0 = fmaxf(mx0, __shfl_xor_sync(0xffffffffu, mx0, 2));
        mx1 = fmaxf(mx1, __shfl_xor_sync(0xffffffffu, mx1, 1));
        mx1 = fmaxf(mx1, __shfl_xor_sync(0xffffffffu, mx1, 2));
        float mn0 = fmaxf(m0s, mx0), mn1 = fmaxf(m1s, mx1);
        float al0 = ex2(m0s - mn0), al1 = ex2(m1s - mn1);
        m0s = mn0; m1s = mn1;
        float sum0 = 0.0f, sum1 = 0.0f;
#pragma unroll
        for (int j = 0; j < 8; j++) {
            sa[j][0] = ex2(sa[j][0] - mn0); sum0 += sa[j][0];
            sa[j][1] = ex2(sa[j][1] - mn0); sum0 += sa[j][1];
            sa[j][2] = ex2(sa[j][2] - mn1); sum1 += sa[j][2];
            sa[j][3] = ex2(sa[j][3] - mn1); sum1 += sa[j][3];
        }
        sum0 += __shfl_xor_sync(0xffffffffu, sum0, 1);
        sum0 += __shfl_xor_sync(0xffffffffu, sum0, 2);
        sum1 += __shfl_xor_sync(0xffffffffu, sum1, 1);
        sum1 += __shfl_xor_sync(0xffffffffu, sum1, 2);
        l0s = l0s * al0 + sum0;
        l1s = l1s * al1 + sum1;
#pragma unroll
        for (int j = 0; j < 8; j++) {
            o[j][0] *= al0; o[j][1] *= al0;
            o[j][2] *= al1; o[j][3] *= al1;
        }

        // ---- pack P into A-fragments (hi/lo) ----
        uint32_t ph[4][4], pl[4][4];
#pragma unroll
        for (int kt = 0; kt < 4; kt++) {
#pragma unroll
            for (int q2 = 0; q2 < 4; q2++) {
                int j  = 2 * kt + (q2 >> 1);
                int rg = (q2 & 1) * 2;
                split2(sa[j][rg], sa[j][rg + 1], ph[kt][q2], pl[kt][q2]);
            }
        }

        // ---- O += P V (3-term) ----
#pragma unroll
        for (int kt = 0; kt < 4; kt++) {
#pragma unroll
            for (int jt = 0; jt < 4; jt++) {
                uint32_t vh4[4], vl4[4];
                uint32_t addr = stb + (2 * KTSZ + (16 * jt + brow_in) * TP
                                       + 16 * kt + bk_half) * 2;
                LDSM_X4(vh4, addr);
                LDSM_X4(vl4, addr + KTSZ * 2);
                MMA16816(o[2 * jt],     ph[kt], vh4);
                MMA16816(o[2 * jt],     pl[kt], vh4);
                MMA16816(o[2 * jt],     ph[kt], vl4);
                MMA16816(o[2 * jt + 1], ph[kt], vh4 + 2);
                MMA16816(o[2 * jt + 1], pl[kt], vh4 + 2);
                MMA16816(o[2 * jt + 1], ph[kt], vl4 + 2);
            }
        }
        __syncthreads();
    }

    // ---- epilogue: normalize, split, store as next GEMM's A ----
    float inv0 = 1.0f / l0s, inv1 = 1.0f / l1s;
    int t0 = 128 * qt + 16 * w + r0;
#pragma unroll
    for (int j = 0; j < 8; j++) {
        int e = h * 64 + 8 * j + c0;
        uint32_t hp, lp;
        split2(o[j][0] * inv0, o[j][1] * inv0, hp, lp);
        size_t idx0 = (size_t)(b * TT + t0) * EMB + e;
        *(uint32_t*)(Oh + idx0) = hp;
        *(uint32_t*)(Ol + idx0) = lp;
        split2(o[j][2] * inv1, o[j][3] * inv1, hp, lp);
        size_t idx1 = (size_t)(b * TT + t0 + 8) * EMB + e;
        *(uint32_t*)(Oh + idx1) = hp;
        *(uint32_t*)(Ol + idx1) = lp;
    }
}

// ---------------------------------------------------------------------------
// Launch
// ---------------------------------------------------------------------------
extern "C" void kernel_launch(void* const* d_in, const int* in_sizes, int n_in,
                              void* d_out, int out_size)
{
    const float* x  = (const float*)d_in[0];
    const float* Wq = (const float*)d_in[1];
    const float* bq = (const float*)d_in[2];
    const float* Wk = (const float*)d_in[3];
    const float* bk = (const float*)d_in[4];
    const float* Wv = (const float*)d_in[5];
    const float* bv = (const float*)d_in[6];
    const float* Wo = (const float*)d_in[7];
    const float* bo = (const float*)d_in[8];
    float* out = (float*)d_out;

    __nv_bfloat16 *ahi, *alo, *whi, *wlo, *qhi, *qlo, *khi, *klo, *vthi, *vtlo;
    cudaGetSymbolAddress((void**)&ahi, g_ahi);
    cudaGetSymbolAddress((void**)&alo, g_alo);
    cudaGetSymbolAddress((void**)&whi, g_whi);
    cudaGetSymbolAddress((void**)&wlo, g_wlo);
    cudaGetSymbolAddress((void**)&qhi, g_qhi);
    cudaGetSymbolAddress((void**)&qlo, g_qlo);
    cudaGetSymbolAddress((void**)&khi, g_khi);
    cudaGetSymbolAddress((void**)&klo, g_klo);
    cudaGetSymbolAddress((void**)&vthi, g_vthi);
    cudaGetSymbolAddress((void**)&vtlo, g_vtlo);

    cudaFuncSetAttribute(gemm_ts, cudaFuncAttributeMaxDynamicSharedMemorySize, GSMEM);
    cudaFuncSetAttribute(attn_tc, cudaFuncAttributeMaxDynamicSharedMemorySize, ASMEM);

    const size_t WS = (size_t)EMB * EMB;

    // Split inputs
    split_x<<<(MM * EMB / 4) / 256, 256>>>(x, ahi, alo);
    dim3 wt_grid(EMB / 32, EMB / 32);
    dim3 wt_blk(32, 8);
    split_wt<<<wt_grid, wt_blk>>>(Wq, whi + 0 * WS, wlo + 0 * WS);
    split_wt<<<wt_grid, wt_blk>>>(Wk, whi + 1 * WS, wlo + 1 * WS);
    split_wt<<<wt_grid, wt_blk>>>(Wv, whi + 2 * WS, wlo + 2 * WS);
    split_wt<<<wt_grid, wt_blk>>>(Wo, whi + 3 * WS, wlo + 3 * WS);

    // QKV projections -> bf16 hi/lo operands for attention
    dim3 ggrid(EMB / 128, MM / 128);    // (8, 64)
    gemm_ts<<<ggrid, 256, GSMEM>>>(ahi, alo, whi + 0 * WS, wlo + 0 * WS, bq,
                                   nullptr, qhi, qlo, 1);
    gemm_ts<<<ggrid, 256, GSMEM>>>(ahi, alo, whi + 1 * WS, wlo + 1 * WS, bk,
                                   nullptr, khi, klo, 1);
    gemm_ts<<<ggrid, 256, GSMEM>>>(ahi, alo, whi + 2 * WS, wlo + 2 * WS, bv,
                                   nullptr, vthi, vtlo, 2);

    // Attention on tensor cores -> writes ahi/alo (A of final GEMM)
    dim3 attn_grid(TT / 128, NH, BB);   // (16, 16, 4)
    attn_tc<<<attn_grid, 256, ASMEM>>>(qhi, qlo, khi, klo, vthi, vtlo, ahi, alo);

    // Output projection (fp32 out)
    gemm_ts<<<ggrid, 256, GSMEM>>>(ahi, alo, whi + 3 * WS, wlo + 3 * WS, bo,
                                   out, nullptr, nullptr, 0);
}

// round 7
// speedup vs baseline: 4.0683x; 1.3983x over previous
#include <cuda_runtime.h>
#include <cuda_fp16.h>
#include <math.h>
#include <stdint.h>

// Problem constants
#define BB   4
#define TT   2048
#define EMB  1024
#define NH   16
#define HD   64
#define MM   (BB * TT)          // 8192 rows

// ---------------------------------------------------------------------------
// Scratch (device globals; no allocation allowed)
// ---------------------------------------------------------------------------
__device__ __half g_ahi[MM * EMB];          // A hi (x, then attn out)
__device__ __half g_alo[MM * EMB];          // A lo
__device__ __half g_whi[4 * EMB * EMB];     // W^T [N][K] hi only, 4 weights
__device__ __half g_qhi[MM * EMB];          // Q [b,h,t,d] hi
__device__ __half g_qlo[MM * EMB];          // Q lo
__device__ __half g_khi[MM * EMB];          // K [b,h,t,d] hi only
__device__ __half g_vthi[MM * EMB];         // V^T [b,h,d,t] hi only

// ---------------------------------------------------------------------------
// Helpers (plain-sm_103-safe PTX: ldmatrix / mma.sync / cp.async)
// ---------------------------------------------------------------------------
__device__ __forceinline__ uint32_t smem_u32(const void* p) {
    uint32_t a;
    asm("{ .reg .u64 t; cvta.to.shared.u64 t, %1; cvt.u32.u64 %0, t; }"
        : "=r"(a) : "l"(p));
    return a;
}

__device__ __forceinline__ float ex2(float x) {
    float r;
    asm("ex2.approx.ftz.f32 %0, %1;" : "=f"(r) : "f"(x));
    return r;
}

#define LDSM_X4(R, addr) \
    asm volatile("ldmatrix.sync.aligned.m8n8.x4.shared.b16 {%0,%1,%2,%3}, [%4];" \
        : "=r"((R)[0]), "=r"((R)[1]), "=r"((R)[2]), "=r"((R)[3]) : "r"(addr))

#define MMA16816(C, A, B) \
    asm volatile("mma.sync.aligned.m16n8k16.row.col.f32.f16.f16.f32 " \
        "{%0,%1,%2,%3}, {%4,%5,%6,%7}, {%8,%9}, {%0,%1,%2,%3};" \
        : "+f"((C)[0]), "+f"((C)[1]), "+f"((C)[2]), "+f"((C)[3]) \
        : "r"((A)[0]), "r"((A)[1]), "r"((A)[2]), "r"((A)[3]), \
          "r"((B)[0]), "r"((B)[1]))

#define CP_ASYNC16(dst, src) \
    asm volatile("cp.async.cg.shared.global [%0], [%1], 16;" :: "r"(dst), "l"(src))
#define CP_COMMIT() asm volatile("cp.async.commit_group;")
#define CP_WAIT1()  asm volatile("cp.async.wait_group 1;")
#define CP_WAIT0()  asm volatile("cp.async.wait_group 0;")

__device__ __forceinline__ void split2h(float x, float y, uint32_t& hp, uint32_t& lp) {
    __half hx = __float2half(x);
    __half hy = __float2half(y);
    __half lx = __float2half(x - __half2float(hx));
    __half ly = __float2half(y - __half2float(hy));
    __half2 h2 = __halves2half2(hx, hy);
    __half2 l2 = __halves2half2(lx, ly);
    hp = *(uint32_t*)&h2;
    lp = *(uint32_t*)&l2;
}
__device__ __forceinline__ uint32_t pack2h(float x, float y) {
    __half2 h2 = __halves2half2(__float2half(x), __float2half(y));
    return *(uint32_t*)&h2;
}

// ---------------------------------------------------------------------------
// split_x: fp32 [8192,1024] row-major -> hi/lo fp16 row-major
// ---------------------------------------------------------------------------
__global__ __launch_bounds__(256)
void split_x(const float* __restrict__ X, __half* __restrict__ hi,
             __half* __restrict__ lo)
{
    int idx = blockIdx.x * 256 + threadIdx.x;
    size_t e = (size_t)idx * 4;
    float4 v = *(const float4*)(X + e);
    uint2 hw, lw;
    split2h(v.x, v.y, hw.x, lw.x);
    split2h(v.z, v.w, hw.y, lw.y);
    *(uint2*)(hi + e) = hw;
    *(uint2*)(lo + e) = lw;
}

// ---------------------------------------------------------------------------
// split_wt: W [K,N] fp32 -> W^T [N,K] fp16 hi only (32x32 smem transpose)
// ---------------------------------------------------------------------------
__global__ __launch_bounds__(256)
void split_wt(const float* __restrict__ W, __half* __restrict__ hi)
{
    __shared__ float ts[32][33];
    const int n0 = blockIdx.x * 32, k0 = blockIdx.y * 32;
    const int tx = threadIdx.x, ty = threadIdx.y;

#pragma unroll
    for (int p = 0; p < 4; p++) {
        int ky = ty + p * 8;
        ts[ky][tx] = W[(size_t)(k0 + ky) * EMB + n0 + tx];
    }
    __syncthreads();
#pragma unroll
    for (int p = 0; p < 4; p++) {
        int ny = ty + p * 8;
        hi[(size_t)(n0 + ny) * EMB + k0 + tx] = __float2half(ts[tx][ny]);
    }
}

// ---------------------------------------------------------------------------
// Tensor-core GEMM via mma.sync (fp16 2-term: (Ah+Al)@Wh).
// CTA 128x128, BK=32, 2-stage cp.async, 8 warps (2x4), warp tile 64x32.
// mode 0: C fp32 [M][N]
// mode 1: Q   -> Chi/Clo fp16 [b,h,t,d]
// mode 3: K   -> Chi fp16 [b,h,t,d] (hi only)
// mode 4: V^T -> Chi fp16 [b,h,d,t] (hi only)
// ---------------------------------------------------------------------------
#define TPAD  40
#define TSZ   (128 * TPAD)
#define GSMEM (2 * 3 * TSZ * 2)    // 61440 bytes

__global__ __launch_bounds__(256, 2)
void gemm_ts(const __half* __restrict__ Ahi, const __half* __restrict__ Alo,
             const __half* __restrict__ Wh, const float* __restrict__ bias,
             float* __restrict__ C, __half* __restrict__ Chi,
             __half* __restrict__ Clo, int mode)
{
    extern __shared__ __align__(128) __half sm[];
    const uint32_t sbase = smem_u32(sm);
    const int tid  = threadIdx.x;
    const int lane = tid & 31;
    const int warp = tid >> 5;
    const int wm = warp >> 2;
    const int wn = warp & 3;
    const int n0 = blockIdx.x * 128;
    const int m0 = blockIdx.y * 128;

    const __half* srcs[3] = {
        Ahi + (size_t)m0 * EMB, Alo + (size_t)m0 * EMB, Wh + (size_t)n0 * EMB
    };

    float acc[4][4][4] = {};

#define LOAD_STAGE(s, k0_)                                                    \
    do {                                                                      \
        _Pragma("unroll")                                                     \
        for (int p = 0; p < 6; p++) {                                         \
            int c = tid + p * 256;                                            \
            int t = c >> 9;                                                   \
            int r = (c >> 2) & 127;                                           \
            int c16 = c & 3;                                                  \
            uint32_t dst = sbase + (((s) * 3 + t) * TSZ + r * TPAD + c16 * 8) * 2; \
            const void* src = srcs[t] + (size_t)r * EMB + (k0_) + c16 * 8;    \
            CP_ASYNC16(dst, src);                                             \
        }                                                                     \
        CP_COMMIT();                                                          \
    } while (0)

    LOAD_STAGE(0, 0);

    const int arow_in = (lane & 7) + ((lane >> 3) & 1) * 8;
    const int ak_half = (lane >> 4) * 8;
    const int bg      = lane >> 3;
    const int brow_in = (lane & 7) + ((bg >> 1) & 1) * 8;
    const int bk_half = (bg & 1) * 8;

    for (int kt = 0; kt < 32; kt++) {
        const int s = kt & 1;
        if (kt < 31) {
            LOAD_STAGE(s ^ 1, (kt + 1) * 32);
            CP_WAIT1();
        } else {
            CP_WAIT0();
        }
        __syncthreads();

        const uint32_t st = sbase + s * 3 * TSZ * 2;
#pragma unroll
        for (int kc = 0; kc < 32; kc += 16) {
            uint32_t ah[4][4], al[4][4], bh[4][2];
#pragma unroll
            for (int i = 0; i < 4; i++) {
                int row = wm * 64 + i * 16 + arow_in;
                uint32_t addr = st + (row * TPAD + kc + ak_half) * 2;
                LDSM_X4(ah[i], addr);
                LDSM_X4(al[i], addr + TSZ * 2);
            }
#pragma unroll
            for (int j = 0; j < 2; j++) {
                int nrow = wn * 32 + j * 16 + brow_in;
                uint32_t addr = st + (2 * TSZ + nrow * TPAD + kc + bk_half) * 2;
                uint32_t r4[4];
                LDSM_X4(r4, addr);
                bh[2 * j][0] = r4[0]; bh[2 * j][1] = r4[1];
                bh[2 * j + 1][0] = r4[2]; bh[2 * j + 1][1] = r4[3];
            }
#pragma unroll
            for (int i = 0; i < 4; i++)
#pragma unroll
                for (int j = 0; j < 4; j++) {
                    MMA16816(acc[i][j], ah[i], bh[j]);
                    MMA16816(acc[i][j], al[i], bh[j]);
                }
        }
        __syncthreads();
    }

    // ---- epilogue ----
    const int ln4 = lane >> 2;
    const int lm4 = lane & 3;
#pragma unroll
    for (int j = 0; j < 4; j++) {
        int n = n0 + wn * 32 + j * 8 + lm4 * 2;
        float2 bj = *(const float2*)(bias + n);
        int hh = n >> 6;
        int d  = n & 63;
#pragma unroll
        for (int i = 0; i < 4; i++) {
#pragma unroll
            for (int half = 0; half < 2; half++) {
                int m = m0 + wm * 64 + i * 16 + ln4 + half * 8;
                float rx = acc[i][j][half * 2 + 0] + bj.x;
                float ry = acc[i][j][half * 2 + 1] + bj.y;
                int b = m >> 11;
                int t = m & (TT - 1);
                if (mode == 0) {
                    *(float2*)(C + (size_t)m * EMB + n) = make_float2(rx, ry);
                } else if (mode == 1) {
                    uint32_t hp, lp;
                    split2h(rx, ry, hp, lp);
                    size_t idx = (((size_t)(b * NH + hh) * TT + t) * HD) + d;
                    *(uint32_t*)(Chi + idx) = hp;
                    *(uint32_t*)(Clo + idx) = lp;
                } else if (mode == 3) {
                    size_t idx = (((size_t)(b * NH + hh) * TT + t) * HD) + d;
                    *(uint32_t*)(Chi + idx) = pack2h(rx, ry);
                } else {
                    size_t idx = (((size_t)(b * NH + hh) * HD + d) * TT) + t;
                    Chi[idx]      = __float2half(rx);
                    Chi[idx + TT] = __float2half(ry);
                }
            }
        }
    }
}

// ---------------------------------------------------------------------------
// Tensor-core causal flash attention, fp16 2-term:
// S = (Qh+Ql)@Kh^T, O += (Ph+Pl)@Vh.
// CTA: 128 q-rows x 64-key chunks, 8 warps x 16 rows.
// ---------------------------------------------------------------------------
#define TP    72
#define QTSZ  (128 * TP)
#define KTSZ  (64 * TP)
#define ASMEM ((2 * QTSZ + 4 * KTSZ) * 2)   // 73728 bytes

#define SCALE2 0.180336880f   // 0.125 * log2(e)

__global__ __launch_bounds__(256, 2)
void attn_tc(const __half* __restrict__ Qh, const __half* __restrict__ Ql,
             const __half* __restrict__ Kh, const __half* __restrict__ Vh,
             __half* __restrict__ Oh, __half* __restrict__ Ol)
{
    extern __shared__ __align__(128) __half smb[];
    const uint32_t sb = smem_u32(smb);
    const int tid = threadIdx.x, lane = tid & 31, w = tid >> 5;
    const int qt = gridDim.x - 1 - blockIdx.x;
    const int h = blockIdx.y, b = blockIdx.z;
    const int bh = b * NH + h;
    const size_t kbase = (size_t)bh * TT * HD;   // Q/K [t][d]
    const size_t vbase = (size_t)bh * HD * TT;   // V^T [d][t]
    const int nch = 2 * qt + 2;

    // ---- Q tiles (hi, lo): 2 tiles x 128 rows x 8 chunks ----
    {
#pragma unroll
        for (int p = 0; p < 8; p++) {
            int c = tid + p * 256;
            int tl = c >> 10, row = (c >> 3) & 127, c16 = c & 7;
            uint32_t dst = sb + ((tl ? QTSZ : 0) + row * TP + c16 * 8) * 2;
            const __half* src =
                (tl ? Ql : Qh) + kbase + (size_t)(128 * qt + row) * HD + c16 * 8;
            CP_ASYNC16(dst, src);
        }
        CP_COMMIT();
    }

    // KV stage: Kh tile [64 key][64 d], Vh tile [64 d][64 key]
#define LOADKV(s, jc_)                                                          \
    do {                                                                        \
        _Pragma("unroll")                                                       \
        for (int p = 0; p < 4; p++) {                                           \
            int c = tid + p * 256;                                              \
            int tl = c >> 9, row = (c >> 3) & 63, c16 = c & 7;                  \
            uint32_t dst = sb + (2 * QTSZ + (s) * 2 * KTSZ + tl * KTSZ          \
                                 + row * TP + c16 * 8) * 2;                     \
            const __half* src;                                                  \
            if (tl == 0)                                                        \
                src = Kh + kbase + (size_t)(64 * (jc_) + row) * HD + c16 * 8;   \
            else                                                                \
                src = Vh + vbase + (size_t)row * TT + 64 * (jc_) + c16 * 8;     \
            CP_ASYNC16(dst, src);                                               \
        }                                                                       \
        CP_COMMIT();                                                            \
    } while (0)

    LOADKV(0, 0);
    CP_WAIT1();              // Q group complete
    __syncthreads();

    const int arow_in = (lane & 7) + ((lane >> 3) & 1) * 8;
    const int ak_half = (lane >> 4) * 8;
    const int bg      = lane >> 3;
    const int brow_in = (lane & 7) + ((bg >> 1) & 1) * 8;
    const int bk_half = (bg & 1) * 8;

    const int r0 = lane >> 2;
    const int c0 = 2 * (lane & 3);
    float m0s = -1e30f, m1s = -1e30f, l0s = 0.0f, l1s = 0.0f;
    float o[8][4] = {};

    for (int jc = 0; jc < nch; jc++) {
        const int s = jc & 1;
        if (jc + 1 < nch) { LOADKV(s ^ 1, jc + 1); CP_WAIT1(); }
        else              { CP_WAIT0(); }
        __syncthreads();

        // warps whose entire row range is above the diagonal: skip compute
        bool active = (64 * jc <= 128 * qt + 16 * w + 15);
        if (active) {
            const uint32_t stb = sb + (2 * QTSZ + s * 2 * KTSZ) * 2;

            // ---- S = Q K^T (2-term) ----
            float sa[8][4] = {};
#pragma unroll
            for (int kt = 0; kt < 4; kt++) {
                uint32_t qh4[4], ql4[4];
                {
                    uint32_t qaddr = sb + ((16 * w + arow_in) * TP + 16 * kt + ak_half) * 2;
                    LDSM_X4(qh4, qaddr);
                    LDSM_X4(ql4, qaddr + QTSZ * 2);
                }
#pragma unroll
                for (int jt = 0; jt < 4; jt++) {
                    uint32_t kh4[4];
                    uint32_t addr = stb + ((16 * jt + brow_in) * TP + 16 * kt + bk_half) * 2;
                    LDSM_X4(kh4, addr);
                    MMA16816(sa[2 * jt],     qh4, kh4);
                    MMA16816(sa[2 * jt],     ql4, kh4);
                    MMA16816(sa[2 * jt + 1], qh4, kh4 + 2);
                    MMA16816(sa[2 * jt + 1], ql4, kh4 + 2);
                }
            }

            // ---- scale (exp2 domain) + causal mask ----
#pragma unroll
            for (int j = 0; j < 8; j++)
#pragma unroll
                for (int rg = 0; rg < 4; rg++) sa[j][rg] *= SCALE2;

            if (jc >= nch - 2) {
                int q0 = 128 * qt + 16 * w + r0;
                int k0 = 64 * jc;
#pragma unroll
                for (int j = 0; j < 8; j++) {
                    int key = k0 + 8 * j + c0;
                    if (key     > q0)     sa[j][0] = -1e30f;
                    if (key + 1 > q0)     sa[j][1] = -1e30f;
                    if (key     > q0 + 8) sa[j][2] = -1e30f;
                    if (key + 1 > q0 + 8) sa[j][3] = -1e30f;
                }
            }

            // ---- online softmax (base-2) ----
            float mx0 = sa[0][0], mx1 = sa[0][2];
#pragma unroll
            for (int j = 0; j < 8; j++) {
                mx0 = fmaxf(mx0, fmaxf(sa[j][0], sa[j][1]));
                mx1 = fmaxf(mx1, fmaxf(sa[j][2], sa[j][3]));
            }
            mx0 = fmaxf(mx0, __shfl_xor_sync(0xffffffffu, mx0, 1));
            mx0 = fmaxf(mx0, __shfl_xor_sync(0xffffffffu, mx0, 2));
            mx1 = fmaxf(mx1, __shfl_xor_sync(0xffffffffu, mx1, 1));
            mx1 = fmaxf(mx1, __shfl_xor_sync(0xffffffffu, mx1, 2));
            float mn0 = fmaxf(m0s, mx0), mn1 = fmaxf(m1s, mx1);
            float al0 = ex2(m0s - mn0), al1 = ex2(m1s - mn1);
            m0s = mn0; m1s = mn1;
            float sum0 = 0.0f, sum1 = 0.0f;
#pragma unroll
            for (int j = 0; j < 8; j++) {
                sa[j][0] = ex2(sa[j][0] - mn0); sum0 += sa[j][0];
                sa[j][1] = ex2(sa[j][1] - mn0); sum0 += sa[j][1];
                sa[j][2] = ex2(sa[j][2] - mn1); sum1 += sa[j][2];
                sa[j][3] = ex2(sa[j][3] - mn1); sum1 += sa[j][3];
            }
            sum0 += __shfl_xor_sync(0xffffffffu, sum0, 1);
            sum0 += __shfl_xor_sync(0xffffffffu, sum0, 2);
            sum1 += __shfl_xor_sync(0xffffffffu, sum1, 1);
            sum1 += __shfl_xor_sync(0xffffffffu, sum1, 2);
            l0s = l0s * al0 + sum0;
            l1s = l1s * al1 + sum1;
#pragma unroll
            for (int j = 0; j < 8; j++) {
                o[j][0] *= al0; o[j][1] *= al0;
                o[j][2] *= al1; o[j][3] *= al1;
            }

            // ---- pack P into A-fragments (hi/lo fp16) ----
            uint32_t ph[4][4], pl[4][4];
#pragma unroll
            for (int kt = 0; kt < 4; kt++) {
#pragma unroll
                for (int q2 = 0; q2 < 4; q2++) {
                    int j  = 2 * kt + (q2 >> 1);
                    int rg = (q2 & 1) * 2;
                    split2h(sa[j][rg], sa[j][rg + 1], ph[kt][q2], pl[kt][q2]);
                }
            }

            // ---- O += P V (2-term) ----
#pragma unroll
            for (int kt = 0; kt < 4; kt++) {
#pragma unroll
                for (int jt = 0; jt < 4; jt++) {
                    uint32_t vh4[4];
                    uint32_t addr = stb + (KTSZ + (16 * jt + brow_in) * TP
                                           + 16 * kt + bk_half) * 2;
                    LDSM_X4(vh4, addr);
                    MMA16816(o[2 * jt],     ph[kt], vh4);
                    MMA16816(o[2 * jt],     pl[kt], vh4);
                    MMA16816(o[2 * jt + 1], ph[kt], vh4 + 2);
                    MMA16816(o[2 * jt + 1], pl[kt], vh4 + 2);
                }
            }
        }
        __syncthreads();
    }

    // ---- epilogue: normalize, split, store as next GEMM's A ----
    float inv0 = 1.0f / l0s, inv1 = 1.0f / l1s;
    int t0 = 128 * qt + 16 * w + r0;
#pragma unroll
    for (int j = 0; j < 8; j++) {
        int e = h * 64 + 8 * j + c0;
        uint32_t hp, lp;
        split2h(o[j][0] * inv0, o[j][1] * inv0, hp, lp);
        size_t idx0 = (size_t)(b * TT + t0) * EMB + e;
        *(uint32_t*)(Oh + idx0) = hp;
        *(uint32_t*)(Ol + idx0) = lp;
        split2h(o[j][2] * inv1, o[j][3] * inv1, hp, lp);
        size_t idx1 = (size_t)(b * TT + t0 + 8) * EMB + e;
        *(uint32_t*)(Oh + idx1) = hp;
        *(uint32_t*)(Ol + idx1) = lp;
    }
}

// ---------------------------------------------------------------------------
// Launch
// ---------------------------------------------------------------------------
extern "C" void kernel_launch(void* const* d_in, const int* in_sizes, int n_in,
                              void* d_out, int out_size)
{
    const float* x  = (const float*)d_in[0];
    const float* Wq = (const float*)d_in[1];
    const float* bq = (const float*)d_in[2];
    const float* Wk = (const float*)d_in[3];
    const float* bk = (const float*)d_in[4];
    const float* Wv = (const float*)d_in[5];
    const float* bv = (const float*)d_in[6];
    const float* Wo = (const float*)d_in[7];
    const float* bo = (const float*)d_in[8];
    float* out = (float*)d_out;

    __half *ahi, *alo, *whi, *qhi, *qlo, *khi, *vthi;
    cudaGetSymbolAddress((void**)&ahi, g_ahi);
    cudaGetSymbolAddress((void**)&alo, g_alo);
    cudaGetSymbolAddress((void**)&whi, g_whi);
    cudaGetSymbolAddress((void**)&qhi, g_qhi);
    cudaGetSymbolAddress((void**)&qlo, g_qlo);
    cudaGetSymbolAddress((void**)&khi, g_khi);
    cudaGetSymbolAddress((void**)&vthi, g_vthi);

    cudaFuncSetAttribute(gemm_ts, cudaFuncAttributeMaxDynamicSharedMemorySize, GSMEM);
    cudaFuncSetAttribute(attn_tc, cudaFuncAttributeMaxDynamicSharedMemorySize, ASMEM);

    const size_t WS = (size_t)EMB * EMB;

    // Split inputs
    split_x<<<(MM * EMB / 4) / 256, 256>>>(x, ahi, alo);
    dim3 wt_grid(EMB / 32, EMB / 32);
    dim3 wt_blk(32, 8);
    split_wt<<<wt_grid, wt_blk>>>(Wq, whi + 0 * WS);
    split_wt<<<wt_grid, wt_blk>>>(Wk, whi + 1 * WS);
    split_wt<<<wt_grid, wt_blk>>>(Wv, whi + 2 * WS);
    split_wt<<<wt_grid, wt_blk>>>(Wo, whi + 3 * WS);

    // QKV projections -> fp16 operands for attention
    dim3 ggrid(EMB / 128, MM / 128);    // (8, 64)
    gemm_ts<<<ggrid, 256, GSMEM>>>(ahi, alo, whi + 0 * WS, bq,
                                   nullptr, qhi, qlo, 1);
    gemm_ts<<<ggrid, 256, GSMEM>>>(ahi, alo, whi + 1 * WS, bk,
                                   nullptr, khi, nullptr, 3);
    gemm_ts<<<ggrid, 256, GSMEM>>>(ahi, alo, whi + 2 * WS, bv,
                                   nullptr, vthi, nullptr, 4);

    // Attention on tensor cores -> writes ahi/alo (A of final GEMM)
    dim3 attn_grid(TT / 128, NH, BB);   // (16, 16, 4)
    attn_tc<<<attn_grid, 256, ASMEM>>>(qhi, qlo, khi, vthi, ahi, alo);

    // Output projection (fp32 out)
    gemm_ts<<<ggrid, 256, GSMEM>>>(ahi, alo, whi + 3 * WS, bo,
                                   out, nullptr, nullptr, 0);
}

// round 8
// speedup vs baseline: 4.7168x; 1.1594x over previous
#include <cuda_runtime.h>
#include <cuda_fp16.h>
#include <math.h>
#include <stdint.h>

// Problem constants
#define BB   4
#define TT   2048
#define EMB  1024
#define NH   16
#define HD   64
#define MM   (BB * TT)          // 8192 rows

// ---------------------------------------------------------------------------
// Scratch (device globals; no allocation allowed)
// ---------------------------------------------------------------------------
__device__ __half g_ahi[MM * EMB];          // A hi (x, then attn out)
__device__ __half g_alo[MM * EMB];          // A lo
__device__ __half g_whi[4 * EMB * EMB];     // W^T [N][K] hi only, 4 weights
__device__ __half g_qhi[MM * EMB];          // Q [b,h,t,d] hi only
__device__ __half g_khi[MM * EMB];          // K [b,h,t,d] hi only
__device__ __half g_vthi[MM * EMB];         // V^T [b,h,d,t] hi only

// ---------------------------------------------------------------------------
// Helpers (plain-sm_103-safe PTX: ldmatrix / mma.sync / cp.async)
// ---------------------------------------------------------------------------
__device__ __forceinline__ uint32_t smem_u32(const void* p) {
    uint32_t a;
    asm("{ .reg .u64 t; cvta.to.shared.u64 t, %1; cvt.u32.u64 %0, t; }"
        : "=r"(a) : "l"(p));
    return a;
}

__device__ __forceinline__ float ex2(float x) {
    float r;
    asm("ex2.approx.ftz.f32 %0, %1;" : "=f"(r) : "f"(x));
    return r;
}

#define LDSM_X4(R, addr) \
    asm volatile("ldmatrix.sync.aligned.m8n8.x4.shared.b16 {%0,%1,%2,%3}, [%4];" \
        : "=r"((R)[0]), "=r"((R)[1]), "=r"((R)[2]), "=r"((R)[3]) : "r"(addr))

#define MMA16816(C, A, B) \
    asm volatile("mma.sync.aligned.m16n8k16.row.col.f32.f16.f16.f32 " \
        "{%0,%1,%2,%3}, {%4,%5,%6,%7}, {%8,%9}, {%0,%1,%2,%3};" \
        : "+f"((C)[0]), "+f"((C)[1]), "+f"((C)[2]), "+f"((C)[3]) \
        : "r"((A)[0]), "r"((A)[1]), "r"((A)[2]), "r"((A)[3]), \
          "r"((B)[0]), "r"((B)[1]))

#define CP_ASYNC16(dst, src) \
    asm volatile("cp.async.cg.shared.global [%0], [%1], 16;" :: "r"(dst), "l"(src))
#define CP_COMMIT() asm volatile("cp.async.commit_group;")
#define CP_WAIT1()  asm volatile("cp.async.wait_group 1;")
#define CP_WAIT0()  asm volatile("cp.async.wait_group 0;")

__device__ __forceinline__ void split2h(float x, float y, uint32_t& hp, uint32_t& lp) {
    __half hx = __float2half(x);
    __half hy = __float2half(y);
    __half lx = __float2half(x - __half2float(hx));
    __half ly = __float2half(y - __half2float(hy));
    __half2 h2 = __halves2half2(hx, hy);
    __half2 l2 = __halves2half2(lx, ly);
    hp = *(uint32_t*)&h2;
    lp = *(uint32_t*)&l2;
}
__device__ __forceinline__ uint32_t pack2h(float x, float y) {
    __half2 h2 = __halves2half2(__float2half(x), __float2half(y));
    return *(uint32_t*)&h2;
}

// ---------------------------------------------------------------------------
// split_x: fp32 [8192,1024] row-major -> hi/lo fp16 row-major
// ---------------------------------------------------------------------------
__global__ __launch_bounds__(256)
void split_x(const float* __restrict__ X, __half* __restrict__ hi,
             __half* __restrict__ lo)
{
    int idx = blockIdx.x * 256 + threadIdx.x;
    size_t e = (size_t)idx * 4;
    float4 v = *(const float4*)(X + e);
    uint2 hw, lw;
    split2h(v.x, v.y, hw.x, lw.x);
    split2h(v.z, v.w, hw.y, lw.y);
    *(uint2*)(hi + e) = hw;
    *(uint2*)(lo + e) = lw;
}

// ---------------------------------------------------------------------------
// split_wt: W [K,N] fp32 -> W^T [N,K] fp16 hi only (32x32 smem transpose)
// ---------------------------------------------------------------------------
__global__ __launch_bounds__(256)
void split_wt(const float* __restrict__ W, __half* __restrict__ hi)
{
    __shared__ float ts[32][33];
    const int n0 = blockIdx.x * 32, k0 = blockIdx.y * 32;
    const int tx = threadIdx.x, ty = threadIdx.y;

#pragma unroll
    for (int p = 0; p < 4; p++) {
        int ky = ty + p * 8;
        ts[ky][tx] = W[(size_t)(k0 + ky) * EMB + n0 + tx];
    }
    __syncthreads();
#pragma unroll
    for (int p = 0; p < 4; p++) {
        int ny = ty + p * 8;
        hi[(size_t)(n0 + ny) * EMB + k0 + tx] = __float2half(ts[tx][ny]);
    }
}

// ---------------------------------------------------------------------------
// Tensor-core GEMM via mma.sync (fp16 2-term: (Ah+Al)@Wh).
// CTA 128x128, BK=64, 2-stage cp.async, 8 warps (2x4), warp tile 64x32.
// mode 0: C fp32 [M][N]
// mode 3: Chi fp16 [b,h,t,d] (hi only)
// mode 4: Chi fp16 [b,h,d,t] (hi only, transposed)
// ---------------------------------------------------------------------------
#define TP2   72
#define TSZ2  (128 * TP2)
#define GSMEM (2 * 3 * TSZ2 * 2)    // 110592 bytes

__global__ __launch_bounds__(256, 2)
void gemm_ts(const __half* __restrict__ Ahi, const __half* __restrict__ Alo,
             const __half* __restrict__ Wh, const float* __restrict__ bias,
             float* __restrict__ C, __half* __restrict__ Chi, int mode)
{
    extern __shared__ __align__(128) __half sm[];
    const uint32_t sbase = smem_u32(sm);
    const int tid  = threadIdx.x;
    const int lane = tid & 31;
    const int warp = tid >> 5;
    const int wm = warp >> 2;
    const int wn = warp & 3;
    const int n0 = blockIdx.x * 128;
    const int m0 = blockIdx.y * 128;

    const __half* srcs[3] = {
        Ahi + (size_t)m0 * EMB, Alo + (size_t)m0 * EMB, Wh + (size_t)n0 * EMB
    };

    float acc[4][4][4] = {};

#define LOAD_STAGE(s, k0_)                                                    \
    do {                                                                      \
        _Pragma("unroll")                                                     \
        for (int p = 0; p < 12; p++) {                                        \
            int c = tid + p * 256;                                            \
            int t = c >> 10;                                                  \
            int r = (c >> 3) & 127;                                           \
            int c8 = c & 7;                                                   \
            uint32_t dst = sbase + (((s) * 3 + t) * TSZ2 + r * TP2 + c8 * 8) * 2; \
            const void* src = srcs[t] + (size_t)r * EMB + (k0_) + c8 * 8;     \
            CP_ASYNC16(dst, src);                                             \
        }                                                                     \
        CP_COMMIT();                                                          \
    } while (0)

    LOAD_STAGE(0, 0);

    const int arow_in = (lane & 7) + ((lane >> 3) & 1) * 8;
    const int ak_half = (lane >> 4) * 8;
    const int bg      = lane >> 3;
    const int brow_in = (lane & 7) + ((bg >> 1) & 1) * 8;
    const int bk_half = (bg & 1) * 8;

    for (int kt = 0; kt < 16; kt++) {
        const int s = kt & 1;
        if (kt < 15) {
            LOAD_STAGE(s ^ 1, (kt + 1) * 64);
            CP_WAIT1();
        } else {
            CP_WAIT0();
        }
        __syncthreads();

        const uint32_t st = sbase + s * 3 * TSZ2 * 2;
#pragma unroll
        for (int kc = 0; kc < 64; kc += 16) {
            uint32_t ah[4][4], al[4][4], bh[4][2];
#pragma unroll
            for (int i = 0; i < 4; i++) {
                int row = wm * 64 + i * 16 + arow_in;
                uint32_t addr = st + (row * TP2 + kc + ak_half) * 2;
                LDSM_X4(ah[i], addr);
                LDSM_X4(al[i], addr + TSZ2 * 2);
            }
#pragma unroll
            for (int j = 0; j < 2; j++) {
                int nrow = wn * 32 + j * 16 + brow_in;
                uint32_t addr = st + (2 * TSZ2 + nrow * TP2 + kc + bk_half) * 2;
                uint32_t r4[4];
                LDSM_X4(r4, addr);
                bh[2 * j][0] = r4[0]; bh[2 * j][1] = r4[1];
                bh[2 * j + 1][0] = r4[2]; bh[2 * j + 1][1] = r4[3];
            }
#pragma unroll
            for (int i = 0; i < 4; i++)
#pragma unroll
                for (int j = 0; j < 4; j++) {
                    MMA16816(acc[i][j], ah[i], bh[j]);
                    MMA16816(acc[i][j], al[i], bh[j]);
                }
        }
        __syncthreads();
    }

    // ---- epilogue ----
    const int ln4 = lane >> 2;
    const int lm4 = lane & 3;
#pragma unroll
    for (int j = 0; j < 4; j++) {
        int n = n0 + wn * 32 + j * 8 + lm4 * 2;
        float2 bj = *(const float2*)(bias + n);
        int hh = n >> 6;
        int d  = n & 63;
#pragma unroll
        for (int i = 0; i < 4; i++) {
#pragma unroll
            for (int half = 0; half < 2; half++) {
                int m = m0 + wm * 64 + i * 16 + ln4 + half * 8;
                float rx = acc[i][j][half * 2 + 0] + bj.x;
                float ry = acc[i][j][half * 2 + 1] + bj.y;
                int b = m >> 11;
                int t = m & (TT - 1);
                if (mode == 0) {
                    *(float2*)(C + (size_t)m * EMB + n) = make_float2(rx, ry);
                } else if (mode == 3) {
                    size_t idx = (((size_t)(b * NH + hh) * TT + t) * HD) + d;
                    *(uint32_t*)(Chi + idx) = pack2h(rx, ry);
                } else {
                    size_t idx = (((size_t)(b * NH + hh) * HD + d) * TT) + t;
                    Chi[idx]      = __float2half(rx);
                    Chi[idx + TT] = __float2half(ry);
                }
            }
        }
    }
}

// ---------------------------------------------------------------------------
// Tensor-core causal flash attention, fp16:
// S = Qh@Kh^T (1 term), O += (Ph+Pl)@Vh (2 terms).
// CTA: 128 q-rows. KV staged 128 keys at a time, consumed as 2x64-key chunks.
// Q fragments resident in registers.
// ---------------------------------------------------------------------------
#define TPK   72
#define TPV   136
#define QTSZ  (128 * TPK)           // 9216 halves
#define KTSZ  (128 * TPK)           // 9216 halves (128 keys x 64 d)
#define VTSZ  (64 * TPV)            // 8704 halves (64 d x 128 keys)
#define STSZ  (KTSZ + VTSZ)         // 17920 halves per stage
#define ASMEM ((QTSZ + 2 * STSZ) * 2)   // 90112 bytes

#define SCALE2 0.180336880f   // 0.125 * log2(e)

__global__ __launch_bounds__(256, 2)
void attn_tc(const __half* __restrict__ Qh, const __half* __restrict__ Kh,
             const __half* __restrict__ Vh,
             __half* __restrict__ Oh, __half* __restrict__ Ol)
{
    extern __shared__ __align__(128) __half smb[];
    const uint32_t sb = smem_u32(smb);
    const int tid = threadIdx.x, lane = tid & 31, w = tid >> 5;
    const int qt = gridDim.x - 1 - blockIdx.x;
    const int h = blockIdx.y, b = blockIdx.z;
    const int bh = b * NH + h;
    const size_t kbase = (size_t)bh * TT * HD;   // Q/K [t][d]
    const size_t vbase = (size_t)bh * HD * TT;   // V^T [d][t]
    const int nst = qt + 1;                      // 128-key stages
    const int nch = 2 * nst;                     // 64-key chunks

    // ---- Q tile (hi only): 128 rows x 64 halves ----
    {
#pragma unroll
        for (int p = 0; p < 4; p++) {
            int c = tid + p * 256;
            int row = c >> 3, c8 = c & 7;
            uint32_t dst = sb + (row * TPK + c8 * 8) * 2;
            const __half* src = Qh + kbase + (size_t)(128 * qt + row) * HD + c8 * 8;
            CP_ASYNC16(dst, src);
        }
        CP_COMMIT();
    }

    // KV stage: K [128 keys][64 d] + V^T [64 d][128 keys]
#define LOADST(s, st_)                                                          \
    do {                                                                        \
        _Pragma("unroll")                                                       \
        for (int p = 0; p < 8; p++) {                                           \
            int c = tid + p * 256;                                              \
            uint32_t dst;                                                       \
            const __half* src;                                                  \
            if (p < 4) {                                                        \
                int row = c >> 3, c8 = c & 7;                                   \
                dst = sb + (QTSZ + (s) * STSZ + row * TPK + c8 * 8) * 2;        \
                src = Kh + kbase + (size_t)(128 * (st_) + row) * HD + c8 * 8;   \
            } else {                                                            \
                int cc = c - 1024;                                              \
                int row = cc >> 4, c16 = cc & 15;                               \
                dst = sb + (QTSZ + (s) * STSZ + KTSZ + row * TPV + c16 * 8) * 2;\
                src = Vh + vbase + (size_t)row * TT + 128 * (st_) + c16 * 8;    \
            }                                                                   \
            CP_ASYNC16(dst, src);                                               \
        }                                                                       \
        CP_COMMIT();                                                            \
    } while (0)

    LOADST(0, 0);
    CP_WAIT1();              // Q group complete
    __syncthreads();

    const int arow_in = (lane & 7) + ((lane >> 3) & 1) * 8;
    const int ak_half = (lane >> 4) * 8;
    const int bg      = lane >> 3;
    const int brow_in = (lane & 7) + ((bg >> 1) & 1) * 8;
    const int bk_half = (bg & 1) * 8;

    // Q fragments resident (16 regs)
    uint32_t qf[4][4];
#pragma unroll
    for (int kt = 0; kt < 4; kt++) {
        uint32_t qaddr = sb + ((16 * w + arow_in) * TPK + 16 * kt + ak_half) * 2;
        LDSM_X4(qf[kt], qaddr);
    }

    const int r0 = lane >> 2;
    const int c0 = 2 * (lane & 3);
    float m0s = -1e30f, m1s = -1e30f, l0s = 0.0f, l1s = 0.0f;
    float o[8][4] = {};

    for (int st = 0; st < nst; st++) {
        const int s = st & 1;
        if (st + 1 < nst) { LOADST(s ^ 1, st + 1); CP_WAIT1(); }
        else              { CP_WAIT0(); }
        __syncthreads();

        const uint32_t kstb = sb + (QTSZ + s * STSZ) * 2;
        const uint32_t vstb = kstb + KTSZ * 2;

#pragma unroll
        for (int sub = 0; sub < 2; sub++) {
            const int jc = 2 * st + sub;
            // warps whose entire row range is above the diagonal: skip
            if (64 * jc > 128 * qt + 16 * w + 15) continue;

            // ---- S = Qh Kh^T (1 term) ----
            float sa[8][4] = {};
#pragma unroll
            for (int kt = 0; kt < 4; kt++) {
#pragma unroll
                for (int jt = 0; jt < 4; jt++) {
                    uint32_t kh4[4];
                    uint32_t addr = kstb + ((64 * sub + 16 * jt + brow_in) * TPK
                                            + 16 * kt + bk_half) * 2;
                    LDSM_X4(kh4, addr);
                    MMA16816(sa[2 * jt],     qf[kt], kh4);
                    MMA16816(sa[2 * jt + 1], qf[kt], kh4 + 2);
                }
            }

            // ---- scale (exp2 domain) + causal mask ----
#pragma unroll
            for (int j = 0; j < 8; j++)
#pragma unroll
                for (int rg = 0; rg < 4; rg++) sa[j][rg] *= SCALE2;

            if (jc >= nch - 2) {
                int q0 = 128 * qt + 16 * w + r0;
                int k0 = 64 * jc;
#pragma unroll
                for (int j = 0; j < 8; j++) {
                    int key = k0 + 8 * j + c0;
                    if (key     > q0)     sa[j][0] = -1e30f;
                    if (key + 1 > q0)     sa[j][1] = -1e30f;
                    if (key     > q0 + 8) sa[j][2] = -1e30f;
                    if (key + 1 > q0 + 8) sa[j][3] = -1e30f;
                }
            }

            // ---- online softmax (base-2) ----
            float mx0 = sa[0][0], mx1 = sa[0][2];
#pragma unroll
            for (int j = 0; j < 8; j++) {
                mx0 = fmaxf(mx0, fmaxf(sa[j][0], sa[j][1]));
                mx1 = fmaxf(mx1, fmaxf(sa[j][2], sa[j][3]));
            }
            mx0 = fmaxf(mx0, __shfl_xor_sync(0xffffffffu, mx0, 1));
            mx0 = fmaxf(mx0, __shfl_xor_sync(0xffffffffu, mx0, 2));
            mx1 = fmaxf(mx1, __shfl_xor_sync(0xffffffffu, mx1, 1));
            mx1 = fmaxf(mx1, __shfl_xor_sync(0xffffffffu, mx1, 2));
            float mn0 = fmaxf(m0s, mx0), mn1 = fmaxf(m1s, mx1);
            bool moved = (mn0 > m0s) || (mn1 > m1s);
            float al0 = ex2(m0s - mn0), al1 = ex2(m1s - mn1);
            m0s = mn0; m1s = mn1;
            float sum0 = 0.0f, sum1 = 0.0f;
#pragma unroll
            for (int j = 0; j < 8; j++) {
                sa[j][0] = ex2(sa[j][0] - mn0); sum0 += sa[j][0];
                sa[j][1] = ex2(sa[j][1] - mn0); sum0 += sa[j][1];
                sa[j][2] = ex2(sa[j][2] - mn1); sum1 += sa[j][2];
                sa[j][3] = ex2(sa[j][3] - mn1); sum1 += sa[j][3];
            }
            sum0 += __shfl_xor_sync(0xffffffffu, sum0, 1);
            sum0 += __shfl_xor_sync(0xffffffffu, sum0, 2);
            sum1 += __shfl_xor_sync(0xffffffffu, sum1, 1);
            sum1 += __shfl_xor_sync(0xffffffffu, sum1, 2);
            l0s = l0s * al0 + sum0;
            l1s = l1s * al1 + sum1;
            if (__ballot_sync(0xffffffffu, moved)) {
#pragma unroll
                for (int j = 0; j < 8; j++) {
                    o[j][0] *= al0; o[j][1] *= al0;
                    o[j][2] *= al1; o[j][3] *= al1;
                }
            }

            // ---- O += (Ph+Pl) V (2 terms), P packed per-kt ----
#pragma unroll
            for (int kt = 0; kt < 4; kt++) {
                uint32_t ph4[4], pl4[4];
#pragma unroll
                for (int q2 = 0; q2 < 4; q2++) {
                    int j  = 2 * kt + (q2 >> 1);
                    int rg = (q2 & 1) * 2;
                    split2h(sa[j][rg], sa[j][rg + 1], ph4[q2], pl4[q2]);
                }
#pragma unroll
                for (int jt = 0; jt < 4; jt++) {
                    uint32_t vh4[4];
                    uint32_t addr = vstb + ((16 * jt + brow_in) * TPV
                                            + 64 * sub + 16 * kt + bk_half) * 2;
                    LDSM_X4(vh4, addr);
                    MMA16816(o[2 * jt],     ph4, vh4);
                    MMA16816(o[2 * jt],     pl4, vh4);
                    MMA16816(o[2 * jt + 1], ph4, vh4 + 2);
                    MMA16816(o[2 * jt + 1], pl4, vh4 + 2);
                }
            }
        }
        __syncthreads();
    }

    // ---- epilogue: normalize, split, store as next GEMM's A ----
    float inv0 = 1.0f / l0s, inv1 = 1.0f / l1s;
    int t0 = 128 * qt + 16 * w + r0;
#pragma unroll
    for (int j = 0; j < 8; j++) {
        int e = h * 64 + 8 * j + c0;
        uint32_t hp, lp;
        split2h(o[j][0] * inv0, o[j][1] * inv0, hp, lp);
        size_t idx0 = (size_t)(b * TT + t0) * EMB + e;
        *(uint32_t*)(Oh + idx0) = hp;
        *(uint32_t*)(Ol + idx0) = lp;
        split2h(o[j][2] * inv1, o[j][3] * inv1, hp, lp);
        size_t idx1 = (size_t)(b * TT + t0 + 8) * EMB + e;
        *(uint32_t*)(Oh + idx1) = hp;
        *(uint32_t*)(Ol + idx1) = lp;
    }
}

// ---------------------------------------------------------------------------
// Launch
// ---------------------------------------------------------------------------
extern "C" void kernel_launch(void* const* d_in, const int* in_sizes, int n_in,
                              void* d_out, int out_size)
{
    const float* x  = (const float*)d_in[0];
    const float* Wq = (const float*)d_in[1];
    const float* bq = (const float*)d_in[2];
    const float* Wk = (const float*)d_in[3];
    const float* bk = (const float*)d_in[4];
    const float* Wv = (const float*)d_in[5];
    const float* bv = (const float*)d_in[6];
    const float* Wo = (const float*)d_in[7];
    const float* bo = (const float*)d_in[8];
    float* out = (float*)d_out;

    __half *ahi, *alo, *whi, *qhi, *khi, *vthi;
    cudaGetSymbolAddress((void**)&ahi, g_ahi);
    cudaGetSymbolAddress((void**)&alo, g_alo);
    cudaGetSymbolAddress((void**)&whi, g_whi);
    cudaGetSymbolAddress((void**)&qhi, g_qhi);
    cudaGetSymbolAddress((void**)&khi, g_khi);
    cudaGetSymbolAddress((void**)&vthi, g_vthi);

    cudaFuncSetAttribute(gemm_ts, cudaFuncAttributeMaxDynamicSharedMemorySize, GSMEM);
    cudaFuncSetAttribute(attn_tc, cudaFuncAttributeMaxDynamicSharedMemorySize, ASMEM);

    const size_t WS = (size_t)EMB * EMB;

    // Split inputs
    split_x<<<(MM * EMB / 4) / 256, 256>>>(x, ahi, alo);
    dim3 wt_grid(EMB / 32, EMB / 32);
    dim3 wt_blk(32, 8);
    split_wt<<<wt_grid, wt_blk>>>(Wq, whi + 0 * WS);
    split_wt<<<wt_grid, wt_blk>>>(Wk, whi + 1 * WS);
    split_wt<<<wt_grid, wt_blk>>>(Wv, whi + 2 * WS);
    split_wt<<<wt_grid, wt_blk>>>(Wo, whi + 3 * WS);

    // QKV projections -> fp16 operands for attention
    dim3 ggrid(EMB / 128, MM / 128);    // (8, 64)
    gemm_ts<<<ggrid, 256, GSMEM>>>(ahi, alo, whi + 0 * WS, bq, nullptr, qhi, 3);
    gemm_ts<<<ggrid, 256, GSMEM>>>(ahi, alo, whi + 1 * WS, bk, nullptr, khi, 3);
    gemm_ts<<<ggrid, 256, GSMEM>>>(ahi, alo, whi + 2 * WS, bv, nullptr, vthi, 4);

    // Attention on tensor cores -> writes ahi/alo (A of final GEMM)
    dim3 attn_grid(TT / 128, NH, BB);   // (16, 16, 4)
    attn_tc<<<attn_grid, 256, ASMEM>>>(qhi, khi, vthi, ahi, alo);

    // Output projection (fp32 out)
    gemm_ts<<<ggrid, 256, GSMEM>>>(ahi, alo, whi + 3 * WS, bo, out, nullptr, 0);
}

// round 9
// speedup vs baseline: 5.4062x; 1.1462x over previous
#include <cuda_runtime.h>
#include <cuda_fp16.h>
#include <math.h>
#include <stdint.h>

// Problem constants
#define BB   4
#define TT   2048
#define EMB  1024
#define NH   16
#define HD   64
#define MM   (BB * TT)          // 8192 rows

// ---------------------------------------------------------------------------
// Scratch (device globals; no allocation allowed)
// ---------------------------------------------------------------------------
__device__ __half g_ahi[MM * EMB];          // A hi (x, then attn out)
__device__ __half g_alo[MM * EMB];          // A lo
__device__ __half g_whi[4 * EMB * EMB];     // W^T [N][K] hi only, 4 weights
__device__ __half g_qhi[MM * EMB];          // Q [b,h,t,d] hi only
__device__ __half g_khi[MM * EMB];          // K [b,h,t,d] hi only
__device__ __half g_vthi[MM * EMB];         // V^T [b,h,d,t] hi only

// ---------------------------------------------------------------------------
// Helpers (plain-sm_103-safe PTX: ldmatrix / mma.sync / cp.async)
// ---------------------------------------------------------------------------
__device__ __forceinline__ uint32_t smem_u32(const void* p) {
    uint32_t a;
    asm("{ .reg .u64 t; cvta.to.shared.u64 t, %1; cvt.u32.u64 %0, t; }"
        : "=r"(a) : "l"(p));
    return a;
}

__device__ __forceinline__ float ex2(float x) {
    float r;
    asm("ex2.approx.ftz.f32 %0, %1;" : "=f"(r) : "f"(x));
    return r;
}

#define LDSM_X4(R, addr) \
    asm volatile("ldmatrix.sync.aligned.m8n8.x4.shared.b16 {%0,%1,%2,%3}, [%4];" \
        : "=r"((R)[0]), "=r"((R)[1]), "=r"((R)[2]), "=r"((R)[3]) : "r"(addr))

#define MMA16816(C, A, B) \
    asm volatile("mma.sync.aligned.m16n8k16.row.col.f32.f16.f16.f32 " \
        "{%0,%1,%2,%3}, {%4,%5,%6,%7}, {%8,%9}, {%0,%1,%2,%3};" \
        : "+f"((C)[0]), "+f"((C)[1]), "+f"((C)[2]), "+f"((C)[3]) \
        : "r"((A)[0]), "r"((A)[1]), "r"((A)[2]), "r"((A)[3]), \
          "r"((B)[0]), "r"((B)[1]))

#define CP_ASYNC16(dst, src) \
    asm volatile("cp.async.cg.shared.global [%0], [%1], 16;" :: "r"(dst), "l"(src))
#define CP_COMMIT() asm volatile("cp.async.commit_group;")
#define CP_WAIT1()  asm volatile("cp.async.wait_group 1;")
#define CP_WAIT0()  asm volatile("cp.async.wait_group 0;")

__device__ __forceinline__ void split2h(float x, float y, uint32_t& hp, uint32_t& lp) {
    __half hx = __float2half(x);
    __half hy = __float2half(y);
    __half lx = __float2half(x - __half2float(hx));
    __half ly = __float2half(y - __half2float(hy));
    __half2 h2 = __halves2half2(hx, hy);
    __half2 l2 = __halves2half2(lx, ly);
    hp = *(uint32_t*)&h2;
    lp = *(uint32_t*)&l2;
}
__device__ __forceinline__ uint32_t pack2h(float x, float y) {
    __half2 h2 = __halves2half2(__float2half(x), __float2half(y));
    return *(uint32_t*)&h2;
}

// ---------------------------------------------------------------------------
// split_x: fp32 [8192,1024] row-major -> hi/lo fp16 row-major
// ---------------------------------------------------------------------------
__global__ __launch_bounds__(256)
void split_x(const float* __restrict__ X, __half* __restrict__ hi,
             __half* __restrict__ lo)
{
    int idx = blockIdx.x * 256 + threadIdx.x;
    size_t e = (size_t)idx * 4;
    float4 v = *(const float4*)(X + e);
    uint2 hw, lw;
    split2h(v.x, v.y, hw.x, lw.x);
    split2h(v.z, v.w, hw.y, lw.y);
    *(uint2*)(hi + e) = hw;
    *(uint2*)(lo + e) = lw;
}

// ---------------------------------------------------------------------------
// split_wt: W [K,N] fp32 -> W^T [N,K] fp16 hi only (32x32 smem transpose)
// ---------------------------------------------------------------------------
__global__ __launch_bounds__(256)
void split_wt(const float* __restrict__ W, __half* __restrict__ hi)
{
    __shared__ float ts[32][33];
    const int n0 = blockIdx.x * 32, k0 = blockIdx.y * 32;
    const int tx = threadIdx.x, ty = threadIdx.y;

#pragma unroll
    for (int p = 0; p < 4; p++) {
        int ky = ty + p * 8;
        ts[ky][tx] = W[(size_t)(k0 + ky) * EMB + n0 + tx];
    }
    __syncthreads();
#pragma unroll
    for (int p = 0; p < 4; p++) {
        int ny = ty + p * 8;
        hi[(size_t)(n0 + ny) * EMB + k0 + tx] = __float2half(ts[tx][ny]);
    }
}

// ---------------------------------------------------------------------------
// Tensor-core GEMM via mma.sync (fp16 2-term A: (Ah+Al)@Wh).
// CTA 128x128, BK=64, 2-stage cp.async, 8 warps (2x4), warp tile 64x32.
// mode 0: single weight (Whb), fp32 out C, grid.x = 8
// mode 5: fused QKV, grid.x = 24; wi = blockIdx.x>>3 selects weight/bias/dst;
//         wi 0 -> Qd [b,h,t,d], wi 1 -> Kd [b,h,t,d], wi 2 -> Vtd [b,h,d,t]
// ---------------------------------------------------------------------------
#define TP2   72
#define TSZ2  (128 * TP2)
#define GSMEM (2 * 3 * TSZ2 * 2)    // 110592 bytes

__global__ __launch_bounds__(256, 2)
void gemm_ts(const __half* __restrict__ Ahi, const __half* __restrict__ Alo,
             const __half* __restrict__ Whb,
             const float* __restrict__ b0, const float* __restrict__ b1,
             const float* __restrict__ b2,
             float* __restrict__ C,
             __half* __restrict__ Qd, __half* __restrict__ Kd,
             __half* __restrict__ Vtd, int mode)
{
    extern __shared__ __align__(128) __half sm[];
    const uint32_t sbase = smem_u32(sm);
    const int tid  = threadIdx.x;
    const int lane = tid & 31;
    const int warp = tid >> 5;
    const int wm = warp >> 2;
    const int wn = warp & 3;
    const int wi = (mode == 5) ? (blockIdx.x >> 3) : 0;
    const int n0 = (mode == 5) ? ((blockIdx.x & 7) * 128) : (blockIdx.x * 128);
    const int m0 = blockIdx.y * 128;

    const __half* Wh = Whb + (size_t)wi * EMB * EMB;
    const float* bias = (wi == 0) ? b0 : (wi == 1) ? b1 : b2;

    const __half* srcs[3] = {
        Ahi + (size_t)m0 * EMB, Alo + (size_t)m0 * EMB, Wh + (size_t)n0 * EMB
    };

    float acc[4][4][4] = {};

#define LOAD_STAGE(s, k0_)                                                    \
    do {                                                                      \
        _Pragma("unroll")                                                     \
        for (int p = 0; p < 12; p++) {                                        \
            int c = tid + p * 256;                                            \
            int t = c >> 10;                                                  \
            int r = (c >> 3) & 127;                                           \
            int c8 = c & 7;                                                   \
            uint32_t dst = sbase + (((s) * 3 + t) * TSZ2 + r * TP2 + c8 * 8) * 2; \
            const void* src = srcs[t] + (size_t)r * EMB + (k0_) + c8 * 8;     \
            CP_ASYNC16(dst, src);                                             \
        }                                                                     \
        CP_COMMIT();                                                          \
    } while (0)

    LOAD_STAGE(0, 0);

    const int arow_in = (lane & 7) + ((lane >> 3) & 1) * 8;
    const int ak_half = (lane >> 4) * 8;
    const int bg      = lane >> 3;
    const int brow_in = (lane & 7) + ((bg >> 1) & 1) * 8;
    const int bk_half = (bg & 1) * 8;

    for (int kt = 0; kt < 16; kt++) {
        const int s = kt & 1;
        if (kt < 15) {
            LOAD_STAGE(s ^ 1, (kt + 1) * 64);
            CP_WAIT1();
        } else {
            CP_WAIT0();
        }
        __syncthreads();

        const uint32_t st = sbase + s * 3 * TSZ2 * 2;
#pragma unroll
        for (int kc = 0; kc < 64; kc += 16) {
            uint32_t ah[4][4], al[4][4], bh[4][2];
#pragma unroll
            for (int i = 0; i < 4; i++) {
                int row = wm * 64 + i * 16 + arow_in;
                uint32_t addr = st + (row * TP2 + kc + ak_half) * 2;
                LDSM_X4(ah[i], addr);
                LDSM_X4(al[i], addr + TSZ2 * 2);
            }
#pragma unroll
            for (int j = 0; j < 2; j++) {
                int nrow = wn * 32 + j * 16 + brow_in;
                uint32_t addr = st + (2 * TSZ2 + nrow * TP2 + kc + bk_half) * 2;
                uint32_t r4[4];
                LDSM_X4(r4, addr);
                bh[2 * j][0] = r4[0]; bh[2 * j][1] = r4[1];
                bh[2 * j + 1][0] = r4[2]; bh[2 * j + 1][1] = r4[3];
            }
#pragma unroll
            for (int i = 0; i < 4; i++)
#pragma unroll
                for (int j = 0; j < 4; j++) {
                    MMA16816(acc[i][j], ah[i], bh[j]);
                    MMA16816(acc[i][j], al[i], bh[j]);
                }
        }
        __syncthreads();
    }

    // ---- epilogue ----
    const int ln4 = lane >> 2;
    const int lm4 = lane & 3;
#pragma unroll
    for (int j = 0; j < 4; j++) {
        int n = n0 + wn * 32 + j * 8 + lm4 * 2;
        float2 bj = *(const float2*)(bias + n);
        int hh = n >> 6;
        int d  = n & 63;
#pragma unroll
        for (int i = 0; i < 4; i++) {
#pragma unroll
            for (int half = 0; half < 2; half++) {
                int m = m0 + wm * 64 + i * 16 + ln4 + half * 8;
                float rx = acc[i][j][half * 2 + 0] + bj.x;
                float ry = acc[i][j][half * 2 + 1] + bj.y;
                int b = m >> 11;
                int t = m & (TT - 1);
                if (mode == 0) {
                    *(float2*)(C + (size_t)m * EMB + n) = make_float2(rx, ry);
                } else if (wi < 2) {
                    __half* dst = (wi == 0) ? Qd : Kd;
                    size_t idx = (((size_t)(b * NH + hh) * TT + t) * HD) + d;
                    *(uint32_t*)(dst + idx) = pack2h(rx, ry);
                } else {
                    size_t idx = (((size_t)(b * NH + hh) * HD + d) * TT) + t;
                    Vtd[idx]      = __float2half(rx);
                    Vtd[idx + TT] = __float2half(ry);
                }
            }
        }
    }
}

// ---------------------------------------------------------------------------
// Tensor-core causal flash attention, fp16:
// S = Qh@Kh^T (1 term), O += Ph@Vh (1 term, P hi only).
// CTA: 128 q-rows. KV staged 128 keys at a time, consumed as 2x64-key chunks.
// Q fragments resident in registers.
// ---------------------------------------------------------------------------
#define TPK   72
#define TPV   136
#define QTSZ  (128 * TPK)           // 9216 halves
#define KTSZ  (128 * TPK)           // 9216 halves (128 keys x 64 d)
#define VTSZ  (64 * TPV)            // 8704 halves (64 d x 128 keys)
#define STSZ  (KTSZ + VTSZ)         // 17920 halves per stage
#define ASMEM ((QTSZ + 2 * STSZ) * 2)   // 90112 bytes

#define SCALE2 0.180336880f   // 0.125 * log2(e)

__global__ __launch_bounds__(256, 2)
void attn_tc(const __half* __restrict__ Qh, const __half* __restrict__ Kh,
             const __half* __restrict__ Vh,
             __half* __restrict__ Oh, __half* __restrict__ Ol)
{
    extern __shared__ __align__(128) __half smb[];
    const uint32_t sb = smem_u32(smb);
    const int tid = threadIdx.x, lane = tid & 31, w = tid >> 5;
    const int qt = gridDim.x - 1 - blockIdx.x;
    const int h = blockIdx.y, b = blockIdx.z;
    const int bh = b * NH + h;
    const size_t kbase = (size_t)bh * TT * HD;   // Q/K [t][d]
    const size_t vbase = (size_t)bh * HD * TT;   // V^T [d][t]
    const int nst = qt + 1;                      // 128-key stages
    const int nch = 2 * nst;                     // 64-key chunks

    // ---- Q tile (hi only): 128 rows x 64 halves ----
    {
#pragma unroll
        for (int p = 0; p < 4; p++) {
            int c = tid + p * 256;
            int row = c >> 3, c8 = c & 7;
            uint32_t dst = sb + (row * TPK + c8 * 8) * 2;
            const __half* src = Qh + kbase + (size_t)(128 * qt + row) * HD + c8 * 8;
            CP_ASYNC16(dst, src);
        }
        CP_COMMIT();
    }

    // KV stage: K [128 keys][64 d] + V^T [64 d][128 keys]
#define LOADST(s, st_)                                                          \
    do {                                                                        \
        _Pragma("unroll")                                                       \
        for (int p = 0; p < 8; p++) {                                           \
            int c = tid + p * 256;                                              \
            uint32_t dst;                                                       \
            const __half* src;                                                  \
            if (p < 4) {                                                        \
                int row = c >> 3, c8 = c & 7;                                   \
                dst = sb + (QTSZ + (s) * STSZ + row * TPK + c8 * 8) * 2;        \
                src = Kh + kbase + (size_t)(128 * (st_) + row) * HD + c8 * 8;   \
            } else {                                                            \
                int cc = c - 1024;                                              \
                int row = cc >> 4, c16 = cc & 15;                               \
                dst = sb + (QTSZ + (s) * STSZ + KTSZ + row * TPV + c16 * 8) * 2;\
                src = Vh + vbase + (size_t)row * TT + 128 * (st_) + c16 * 8;    \
            }                                                                   \
            CP_ASYNC16(dst, src);                                               \
        }                                                                       \
        CP_COMMIT();                                                            \
    } while (0)

    LOADST(0, 0);
    CP_WAIT1();              // Q group complete
    __syncthreads();

    const int arow_in = (lane & 7) + ((lane >> 3) & 1) * 8;
    const int ak_half = (lane >> 4) * 8;
    const int bg      = lane >> 3;
    const int brow_in = (lane & 7) + ((bg >> 1) & 1) * 8;
    const int bk_half = (bg & 1) * 8;

    // Q fragments resident (16 regs)
    uint32_t qf[4][4];
#pragma unroll
    for (int kt = 0; kt < 4; kt++) {
        uint32_t qaddr = sb + ((16 * w + arow_in) * TPK + 16 * kt + ak_half) * 2;
        LDSM_X4(qf[kt], qaddr);
    }

    const int r0 = lane >> 2;
    const int c0 = 2 * (lane & 3);
    float m0s = -1e30f, m1s = -1e30f, l0s = 0.0f, l1s = 0.0f;
    float o[8][4] = {};

    for (int st = 0; st < nst; st++) {
        const int s = st & 1;
        if (st + 1 < nst) { LOADST(s ^ 1, st + 1); CP_WAIT1(); }
        else              { CP_WAIT0(); }
        __syncthreads();

        const uint32_t kstb = sb + (QTSZ + s * STSZ) * 2;
        const uint32_t vstb = kstb + KTSZ * 2;

#pragma unroll
        for (int sub = 0; sub < 2; sub++) {
            const int jc = 2 * st + sub;
            // warps whose entire row range is above the diagonal: skip
            if (64 * jc > 128 * qt + 16 * w + 15) continue;

            // ---- S = Qh Kh^T (1 term) ----
            float sa[8][4] = {};
#pragma unroll
            for (int kt = 0; kt < 4; kt++) {
#pragma unroll
                for (int jt = 0; jt < 4; jt++) {
                    uint32_t kh4[4];
                    uint32_t addr = kstb + ((64 * sub + 16 * jt + brow_in) * TPK
                                            + 16 * kt + bk_half) * 2;
                    LDSM_X4(kh4, addr);
                    MMA16816(sa[2 * jt],     qf[kt], kh4);
                    MMA16816(sa[2 * jt + 1], qf[kt], kh4 + 2);
                }
            }

            // ---- scale (exp2 domain) + causal mask ----
#pragma unroll
            for (int j = 0; j < 8; j++)
#pragma unroll
                for (int rg = 0; rg < 4; rg++) sa[j][rg] *= SCALE2;

            if (jc >= nch - 2) {
                int q0 = 128 * qt + 16 * w + r0;
                int k0 = 64 * jc;
#pragma unroll
                for (int j = 0; j < 8; j++) {
                    int key = k0 + 8 * j + c0;
                    if (key     > q0)     sa[j][0] = -1e30f;
                    if (key + 1 > q0)     sa[j][1] = -1e30f;
                    if (key     > q0 + 8) sa[j][2] = -1e30f;
                    if (key + 1 > q0 + 8) sa[j][3] = -1e30f;
                }
            }

            // ---- online softmax (base-2) ----
            float mx0 = sa[0][0], mx1 = sa[0][2];
#pragma unroll
            for (int j = 0; j < 8; j++) {
                mx0 = fmaxf(mx0, fmaxf(sa[j][0], sa[j][1]));
                mx1 = fmaxf(mx1, fmaxf(sa[j][2], sa[j][3]));
            }
            mx0 = fmaxf(mx0, __shfl_xor_sync(0xffffffffu, mx0, 1));
            mx0 = fmaxf(mx0, __shfl_xor_sync(0xffffffffu, mx0, 2));
            mx1 = fmaxf(mx1, __shfl_xor_sync(0xffffffffu, mx1, 1));
            mx1 = fmaxf(mx1, __shfl_xor_sync(0xffffffffu, mx1, 2));
            float mn0 = fmaxf(m0s, mx0), mn1 = fmaxf(m1s, mx1);
            bool moved = (mn0 > m0s) || (mn1 > m1s);
            float al0 = ex2(m0s - mn0), al1 = ex2(m1s - mn1);
            m0s = mn0; m1s = mn1;
            float sum0 = 0.0f, sum1 = 0.0f;
#pragma unroll
            for (int j = 0; j < 8; j++) {
                sa[j][0] = ex2(sa[j][0] - mn0); sum0 += sa[j][0];
                sa[j][1] = ex2(sa[j][1] - mn0); sum0 += sa[j][1];
                sa[j][2] = ex2(sa[j][2] - mn1); sum1 += sa[j][2];
                sa[j][3] = ex2(sa[j][3] - mn1); sum1 += sa[j][3];
            }
            sum0 += __shfl_xor_sync(0xffffffffu, sum0, 1);
            sum0 += __shfl_xor_sync(0xffffffffu, sum0, 2);
            sum1 += __shfl_xor_sync(0xffffffffu, sum1, 1);
            sum1 += __shfl_xor_sync(0xffffffffu, sum1, 2);
            l0s = l0s * al0 + sum0;
            l1s = l1s * al1 + sum1;
            if (__ballot_sync(0xffffffffu, moved)) {
#pragma unroll
                for (int j = 0; j < 8; j++) {
                    o[j][0] *= al0; o[j][1] *= al0;
                    o[j][2] *= al1; o[j][3] *= al1;
                }
            }

            // ---- O += Ph V (1 term, P hi only) ----
#pragma unroll
            for (int kt = 0; kt < 4; kt++) {
                uint32_t ph4[4];
#pragma unroll
                for (int q2 = 0; q2 < 4; q2++) {
                    int j  = 2 * kt + (q2 >> 1);
                    int rg = (q2 & 1) * 2;
                    ph4[q2] = pack2h(sa[j][rg], sa[j][rg + 1]);
                }
#pragma unroll
                for (int jt = 0; jt < 4; jt++) {
                    uint32_t vh4[4];
                    uint32_t addr = vstb + ((16 * jt + brow_in) * TPV
                                            + 64 * sub + 16 * kt + bk_half) * 2;
                    LDSM_X4(vh4, addr);
                    MMA16816(o[2 * jt],     ph4, vh4);
                    MMA16816(o[2 * jt + 1], ph4, vh4 + 2);
                }
            }
        }
        __syncthreads();
    }

    // ---- epilogue: normalize, split, store as next GEMM's A ----
    float inv0 = 1.0f / l0s, inv1 = 1.0f / l1s;
    int t0 = 128 * qt + 16 * w + r0;
#pragma unroll
    for (int j = 0; j < 8; j++) {
        int e = h * 64 + 8 * j + c0;
        uint32_t hp, lp;
        split2h(o[j][0] * inv0, o[j][1] * inv0, hp, lp);
        size_t idx0 = (size_t)(b * TT + t0) * EMB + e;
        *(uint32_t*)(Oh + idx0) = hp;
        *(uint32_t*)(Ol + idx0) = lp;
        split2h(o[j][2] * inv1, o[j][3] * inv1, hp, lp);
        size_t idx1 = (size_t)(b * TT + t0 + 8) * EMB + e;
        *(uint32_t*)(Oh + idx1) = hp;
        *(uint32_t*)(Ol + idx1) = lp;
    }
}

// ---------------------------------------------------------------------------
// Launch
// ---------------------------------------------------------------------------
extern "C" void kernel_launch(void* const* d_in, const int* in_sizes, int n_in,
                              void* d_out, int out_size)
{
    const float* x  = (const float*)d_in[0];
    const float* Wq = (const float*)d_in[1];
    const float* bq = (const float*)d_in[2];
    const float* Wk = (const float*)d_in[3];
    const float* bk = (const float*)d_in[4];
    const float* Wv = (const float*)d_in[5];
    const float* bv = (const float*)d_in[6];
    const float* Wo = (const float*)d_in[7];
    const float* bo = (const float*)d_in[8];
    float* out = (float*)d_out;

    __half *ahi, *alo, *whi, *qhi, *khi, *vthi;
    cudaGetSymbolAddress((void**)&ahi, g_ahi);
    cudaGetSymbolAddress((void**)&alo, g_alo);
    cudaGetSymbolAddress((void**)&whi, g_whi);
    cudaGetSymbolAddress((void**)&qhi, g_qhi);
    cudaGetSymbolAddress((void**)&khi, g_khi);
    cudaGetSymbolAddress((void**)&vthi, g_vthi);

    cudaFuncSetAttribute(gemm_ts, cudaFuncAttributeMaxDynamicSharedMemorySize, GSMEM);
    cudaFuncSetAttribute(attn_tc, cudaFuncAttributeMaxDynamicSharedMemorySize, ASMEM);

    const size_t WS = (size_t)EMB * EMB;

    // Split inputs
    split_x<<<(MM * EMB / 4) / 256, 256>>>(x, ahi, alo);
    dim3 wt_grid(EMB / 32, EMB / 32);
    dim3 wt_blk(32, 8);
    split_wt<<<wt_grid, wt_blk>>>(Wq, whi + 0 * WS);
    split_wt<<<wt_grid, wt_blk>>>(Wk, whi + 1 * WS);
    split_wt<<<wt_grid, wt_blk>>>(Wv, whi + 2 * WS);
    split_wt<<<wt_grid, wt_blk>>>(Wo, whi + 3 * WS);

    // Fused QKV projection (one launch, 24 n-tiles = 3 weights x 8)
    dim3 qkv_grid(24, MM / 128);        // (24, 64)
    gemm_ts<<<qkv_grid, 256, GSMEM>>>(ahi, alo, whi, bq, bk, bv,
                                      nullptr, qhi, khi, vthi, 5);

    // Attention on tensor cores -> writes ahi/alo (A of final GEMM)
    dim3 attn_grid(TT / 128, NH, BB);   // (16, 16, 4)
    attn_tc<<<attn_grid, 256, ASMEM>>>(qhi, khi, vthi, ahi, alo);

    // Output projection (fp32 out)
    dim3 ggrid(EMB / 128, MM / 128);    // (8, 64)
    gemm_ts<<<ggrid, 256, GSMEM>>>(ahi, alo, whi + 3 * WS, bo, nullptr, nullptr,
                                   out, nullptr, nullptr, nullptr, 0);
}